// round 12
// baseline (speedup 1.0000x reference)
#include <cuda_runtime.h>
#include <cuda_bf16.h>
#include <cstdint>

#define BB   4
#define SS   1024
#define HID  1024
#define NH   16
#define HD   64
#define MTOT (BB*SS)

// ---------------- scratch ----------------
__device__ __nv_bfloat16 g_bx1[MTOT*HID];
__device__ __nv_bfloat16 g_bx2[MTOT*HID];
__device__ __nv_bfloat16 g_bw [4*HID*HID];      // Wq,Wk,Wv,Wo (bf16, contiguous)
__device__ __nv_bfloat16 g_bq [MTOT*HID];
__device__ __nv_bfloat16 g_bkv[MTOT*2*HID];     // fused [K | V] rows, stride 2048
__device__ __nv_bfloat16 g_bao[MTOT*HID];
__device__ float         g_o2 [MTOT*HID];
__device__ float         g_part[64*BB*HID];

// ---------------- helpers ----------------
__device__ __forceinline__ uint32_t f2bf2(float lo, float hi){
    uint32_t r; asm("cvt.rn.bf16x2.f32 %0, %1, %2;" : "=r"(r) : "f"(hi), "f"(lo));
    return r;
}
__device__ __forceinline__ float ex2f(float x){
    float y; asm("ex2.approx.ftz.f32 %0, %1;" : "=f"(y) : "f"(x)); return y;
}
__device__ __forceinline__ void mma_bf16(float* d,
    const uint32_t* a, uint32_t b0, uint32_t b1)
{
    asm volatile(
        "mma.sync.aligned.m16n8k16.row.col.f32.bf16.bf16.f32 "
        "{%0,%1,%2,%3}, {%4,%5,%6,%7}, {%8,%9}, {%0,%1,%2,%3};"
        : "+f"(d[0]), "+f"(d[1]), "+f"(d[2]), "+f"(d[3])
        : "r"(a[0]), "r"(a[1]), "r"(a[2]), "r"(a[3]), "r"(b0), "r"(b1));
}
__device__ __forceinline__ void ldsm_x4(uint32_t* r, uint32_t a){
    asm volatile("ldmatrix.sync.aligned.m8n8.x4.shared.b16 {%0,%1,%2,%3}, [%4];"
                 : "=r"(r[0]), "=r"(r[1]), "=r"(r[2]), "=r"(r[3]) : "r"(a));
}
__device__ __forceinline__ void ldsm_x4t(uint32_t* r, uint32_t a){
    asm volatile("ldmatrix.sync.aligned.m8n8.x4.trans.shared.b16 {%0,%1,%2,%3}, [%4];"
                 : "=r"(r[0]), "=r"(r[1]), "=r"(r[2]), "=r"(r[3]) : "r"(a));
}
__device__ __forceinline__ void cp16(uint32_t dst, const void* src){
    asm volatile("cp.async.cg.shared.global [%0], [%1], 16;" :: "r"(dst), "l"(src));
}
#define CP_COMMIT asm volatile("cp.async.commit_group;" ::: "memory")
#define CP_WAIT1  asm volatile("cp.async.wait_group 1;" ::: "memory")

// =============================================================================
// conversions
// =============================================================================
__global__ __launch_bounds__(256) void conv_x(
    const float* __restrict__ s0, const float* __restrict__ s1,
    __nv_bfloat16* __restrict__ d0, __nv_bfloat16* __restrict__ d1)
{
    const float* s = blockIdx.y ? s1 : s0;
    __nv_bfloat16* d = blockIdx.y ? d1 : d0;
    int i = (blockIdx.x * 256 + threadIdx.x) * 4;
    float4 v = *(const float4*)(s + i);
    *(uint2*)(d + i) = make_uint2(f2bf2(v.x, v.y), f2bf2(v.z, v.w));
}
__global__ __launch_bounds__(256) void conv_w(
    const float* __restrict__ w0, const float* __restrict__ w1,
    const float* __restrict__ w2, const float* __restrict__ w3,
    __nv_bfloat16* __restrict__ d)
{
    const float* s = blockIdx.y == 0 ? w0 : blockIdx.y == 1 ? w1 :
                     blockIdx.y == 2 ? w2 : w3;
    int i = (blockIdx.x * 256 + threadIdx.x) * 4;
    float4 v = *(const float4*)(s + i);
    *(uint2*)(d + (size_t)blockIdx.y * HID * HID + i) =
        make_uint2(f2bf2(v.x, v.y), f2bf2(v.z, v.w));
}

// =============================================================================
// bf16 GEMM core: 128x128x64 CTA tile, 4 warps, warp tile 64x64.
// 3 smem buffers, prefetch distance 2, ONE syncthreads per chunk.
// =============================================================================
#define TBM 128
#define TBN 128
#define TBK 64
#define GPD 72
#define NBUF 3
#define NCH (HID/TBK)                        // 16
#define GEMM_SMEM (NBUF*(TBM+TBN)*GPD*2)     // 110592

__device__ __forceinline__ void gemm_stage(
    const __nv_bfloat16* __restrict__ A, const __nv_bfloat16* __restrict__ W,
    int bm, int bn, int kt, int buf, int tid, uint32_t uBase)
{
    const int k0 = kt * TBK;
    const uint32_t uA = uBase + (uint32_t)buf * TBM * GPD * 2;
    const uint32_t uB = uBase + (uint32_t)(NBUF * TBM + buf * TBN) * GPD * 2;
#pragma unroll
    for (int i = 0; i < 8; ++i) {
        int idx = tid + i * 128;
        int row = idx >> 3, cc = (idx & 7) * 8;
        cp16(uA + (uint32_t)(row * GPD + cc) * 2,
             A + (size_t)(bm + row) * HID + k0 + cc);
        cp16(uB + (uint32_t)(row * GPD + cc) * 2,
             W + (size_t)(bn + row) * HID + k0 + cc);
    }
}

template<bool OBF>
__device__ __forceinline__ void gemm_core(
    const __nv_bfloat16* __restrict__ A, const __nv_bfloat16* __restrict__ W,
    void* __restrict__ Cv, int ldc, float scale, int bm, int bn, uint32_t uBase)
{
    const int tid = threadIdx.x, lane = tid & 31, wid = tid >> 5;
    const int wm = (wid & 1) * 64, wn = (wid >> 1) * 64;
    const int g = lane >> 2, t4 = lane & 3;

    float acc[4][8][4];
#pragma unroll
    for (int mt = 0; mt < 4; ++mt)
#pragma unroll
        for (int nt = 0; nt < 8; ++nt)
#pragma unroll
            for (int i = 0; i < 4; ++i) acc[mt][nt][i] = 0.f;

#pragma unroll
    for (int p = 0; p < 2; ++p) {
        gemm_stage(A, W, bm, bn, p, p, tid, uBase);
        CP_COMMIT;
    }

    for (int kt = 0; kt < NCH; ++kt) {
        const int buf = kt % NBUF;
        const uint32_t uA = uBase + (uint32_t)buf * TBM * GPD * 2;
        const uint32_t uB = uBase + (uint32_t)(NBUF * TBM + buf * TBN) * GPD * 2;

        CP_WAIT1;
        __syncthreads();

        if (kt + 2 < NCH)
            gemm_stage(A, W, bm, bn, kt + 2, (kt + 2) % NBUF, tid, uBase);
        CP_COMMIT;

#pragma unroll
        for (int ks = 0; ks < 4; ++ks) {
            const int kk = ks * 16;
            uint32_t af[4][4], bf[4][4];
#pragma unroll
            for (int mt = 0; mt < 4; ++mt) {
                int row = wm + mt * 16 + (lane & 15);
                int col = kk + ((lane >> 4) << 3);
                ldsm_x4(af[mt], uA + (uint32_t)(row * GPD + col) * 2);
            }
#pragma unroll
            for (int np = 0; np < 4; ++np) {
                int row = wn + np * 16 + ((lane & 16) >> 1) + (lane & 7);
                int col = kk + (lane & 8);
                ldsm_x4(bf[np], uB + (uint32_t)(row * GPD + col) * 2);
            }
#pragma unroll
            for (int mt = 0; mt < 4; ++mt)
#pragma unroll
                for (int np = 0; np < 4; ++np) {
                    mma_bf16(acc[mt][2 * np],     af[mt], bf[np][0], bf[np][1]);
                    mma_bf16(acc[mt][2 * np + 1], af[mt], bf[np][2], bf[np][3]);
                }
        }
    }

    if (OBF) {
        __nv_bfloat16* C = (__nv_bfloat16*)Cv;
#pragma unroll
        for (int mt = 0; mt < 4; ++mt) {
            int r0 = bm + wm + mt * 16 + g;
#pragma unroll
            for (int nt = 0; nt < 8; ++nt) {
                int c = bn + wn + nt * 8 + 2 * t4;
                *(uint32_t*)(C + (size_t)r0 * ldc + c) =
                    f2bf2(acc[mt][nt][0] * scale, acc[mt][nt][1] * scale);
                *(uint32_t*)(C + (size_t)(r0 + 8) * ldc + c) =
                    f2bf2(acc[mt][nt][2] * scale, acc[mt][nt][3] * scale);
            }
        }
    } else {
        float* C = (float*)Cv;
#pragma unroll
        for (int mt = 0; mt < 4; ++mt) {
            int r0 = bm + wm + mt * 16 + g;
#pragma unroll
            for (int nt = 0; nt < 8; ++nt) {
                int c = bn + wn + nt * 8 + 2 * t4;
                *(float2*)(C + (size_t)r0 * ldc + c)       = make_float2(acc[mt][nt][0], acc[mt][nt][1]);
                *(float2*)(C + (size_t)(r0 + 8) * ldc + c) = make_float2(acc[mt][nt][2], acc[mt][nt][3]);
            }
        }
    }
}

// fused Q + KV projection: blockIdx.x < 8 -> Q (x1*Wq, scaled), else KV (x2*Wkv)
__global__ __launch_bounds__(128, 2) void gemm_qkv(
    const __nv_bfloat16* __restrict__ x1, const __nv_bfloat16* __restrict__ x2,
    const __nv_bfloat16* __restrict__ Wq, const __nv_bfloat16* __restrict__ Wkv,
    __nv_bfloat16* __restrict__ Cq, __nv_bfloat16* __restrict__ Ckv, float qscale)
{
    extern __shared__ __nv_bfloat16 smg[];
    const uint32_t uBase = (uint32_t)__cvta_generic_to_shared(smg);
    const int bm = blockIdx.y * TBM;
    if (blockIdx.x < 8) {
        gemm_core<true>(x1, Wq, Cq, HID, qscale, bm, blockIdx.x * TBN, uBase);
    } else {
        gemm_core<true>(x2, Wkv, Ckv, 2 * HID, 1.0f, bm, (blockIdx.x - 8) * TBN, uBase);
    }
}

// O projection (fp32 out)
__global__ __launch_bounds__(128, 2) void gemm_o(
    const __nv_bfloat16* __restrict__ A, const __nv_bfloat16* __restrict__ W,
    float* __restrict__ C)
{
    extern __shared__ __nv_bfloat16 smg[];
    const uint32_t uBase = (uint32_t)__cvta_generic_to_shared(smg);
    gemm_core<false>(A, W, C, HID, 1.0f, blockIdx.y * TBM, blockIdx.x * TBN, uBase);
}

// =============================================================================
// bf16 flash attention: 4 warps x 32 query rows, 64-key tiles split into two
// 32-key halves (small sacc -> 3 CTAs/SM). 3 smem buffers, 1 sync per tile.
// grid (S1/128, H, B)
// =============================================================================
#define ANBUF 3
#define KP 72
#define AKV (64*KP*2)                       // bytes per 64-row tile
#define ATT_SMEM (ANBUF*2*AKV + ANBUF*64*4) // 56064

__device__ __forceinline__ void attn_stage(
    const __nv_bfloat16* __restrict__ Kb, const __nv_bfloat16* __restrict__ Vb,
    const int* __restrict__ mb, int t0, int buf, int tid,
    uint32_t uK, uint32_t uV, float* mskf)
{
#pragma unroll
    for (int i = 0; i < 4; ++i) {
        int idx = tid + i * 128;
        int row = idx >> 3, cc = (idx & 7) * 8;
        cp16(uK + (uint32_t)((buf * 64 + row) * KP + cc) * 2,
             Kb + (size_t)(t0 + row) * 2048 + cc);
        cp16(uV + (uint32_t)((buf * 64 + row) * KP + cc) * 2,
             Vb + (size_t)(t0 + row) * 2048 + cc);
    }
    if (tid < 64) mskf[buf * 64 + tid] = mb[t0 + tid] ? 0.f : -1e9f;
}

__global__ __launch_bounds__(128, 3) void attn_bf16(
    const __nv_bfloat16* __restrict__ Q, const __nv_bfloat16* __restrict__ KVg,
    const int* __restrict__ mask, __nv_bfloat16* __restrict__ O)
{
    extern __shared__ char sma[];
    const uint32_t uK = (uint32_t)__cvta_generic_to_shared(sma);
    const uint32_t uV = uK + ANBUF * AKV;
    float* mskf = (float*)(sma + 2 * ANBUF * AKV);

    const int m0 = blockIdx.x * 128;
    const int h  = blockIdx.y, b = blockIdx.z;
    const int tid = threadIdx.x, lane = tid & 31, wid = tid >> 5;
    const int g = lane >> 2, t4 = lane & 3;

    // Q fragments: 32 rows per warp, 2 m16 tiles
    uint32_t qa[4][2][4];
    const __nv_bfloat16* Qb = Q + (size_t)(b * SS + m0 + wid * 32) * HID + h * HD;
#pragma unroll
    for (int kc = 0; kc < 4; ++kc) {
        int k0 = kc * 16 + t4 * 2;
#pragma unroll
        for (int mt = 0; mt < 2; ++mt) {
            const __nv_bfloat16* Qm = Qb + (size_t)(mt * 16) * HID;
            qa[kc][mt][0] = *(const uint32_t*)(Qm + (size_t)g * HID + k0);
            qa[kc][mt][1] = *(const uint32_t*)(Qm + (size_t)(g + 8) * HID + k0);
            qa[kc][mt][2] = *(const uint32_t*)(Qm + (size_t)g * HID + k0 + 8);
            qa[kc][mt][3] = *(const uint32_t*)(Qm + (size_t)(g + 8) * HID + k0 + 8);
        }
    }

    float oacc[2][8][4];
#pragma unroll
    for (int mt = 0; mt < 2; ++mt)
#pragma unroll
        for (int nt = 0; nt < 8; ++nt)
#pragma unroll
            for (int i = 0; i < 4; ++i) oacc[mt][nt][i] = 0.f;
    float lp[2][2] = {{0.f, 0.f}, {0.f, 0.f}};

    const int* mb = mask + b * SS;
    const __nv_bfloat16* Kb = KVg + (size_t)(b * SS) * 2048 + h * HD;
    const __nv_bfloat16* Vb = Kb + 1024;

#pragma unroll
    for (int p = 0; p < 2; ++p) {
        attn_stage(Kb, Vb, mb, p * 64, p, tid, uK, uV, mskf);
        CP_COMMIT;
    }

    for (int t = 0; t < 16; ++t) {
        const int buf = t % ANBUF;
        CP_WAIT1;
        __syncthreads();

        if (t + 2 < 16)
            attn_stage(Kb, Vb, mb, (t + 2) * 64, (t + 2) % ANBUF, tid, uK, uV, mskf);
        CP_COMMIT;

        // two 32-key halves: QK -> exp -> PV each (keeps sacc small)
#pragma unroll
        for (int h32 = 0; h32 < 2; ++h32) {
            const int rbase = buf * 64 + h32 * 32;

            // ---- S = Q K^T : per warp 32x32 ----
            float sacc[2][4][4];
#pragma unroll
            for (int mt = 0; mt < 2; ++mt)
#pragma unroll
                for (int nt = 0; nt < 4; ++nt)
#pragma unroll
                    for (int i = 0; i < 4; ++i) sacc[mt][nt][i] = 0.f;
#pragma unroll
            for (int ks = 0; ks < 4; ++ks) {
                const int kk = ks * 16;
#pragma unroll
                for (int np = 0; np < 2; ++np) {
                    int row = rbase + np * 16 + ((lane & 16) >> 1) + (lane & 7);
                    int col = kk + (lane & 8);
                    uint32_t bf[4];
                    ldsm_x4(bf, uK + (uint32_t)(row * KP + col) * 2);
#pragma unroll
                    for (int mt = 0; mt < 2; ++mt) {
                        mma_bf16(sacc[mt][2 * np],     qa[ks][mt], bf[0], bf[1]);
                        mma_bf16(sacc[mt][2 * np + 1], qa[ks][mt], bf[2], bf[3]);
                    }
                }
            }

            // ---- p = exp2(s + mask) ----
#pragma unroll
            for (int mt = 0; mt < 2; ++mt)
#pragma unroll
                for (int nt = 0; nt < 4; ++nt) {
                    int c = h32 * 32 + nt * 8 + 2 * t4;
                    float a0 = mskf[buf * 64 + c], a1 = mskf[buf * 64 + c + 1];
                    sacc[mt][nt][0] = ex2f(sacc[mt][nt][0] + a0);
                    sacc[mt][nt][1] = ex2f(sacc[mt][nt][1] + a1);
                    sacc[mt][nt][2] = ex2f(sacc[mt][nt][2] + a0);
                    sacc[mt][nt][3] = ex2f(sacc[mt][nt][3] + a1);
                    lp[mt][0] += sacc[mt][nt][0] + sacc[mt][nt][1];
                    lp[mt][1] += sacc[mt][nt][2] + sacc[mt][nt][3];
                }

            // ---- O += P V (P in registers) ----
#pragma unroll
            for (int kt = 0; kt < 2; ++kt) {
                uint32_t pf[2][4];
#pragma unroll
                for (int mt = 0; mt < 2; ++mt) {
                    pf[mt][0] = f2bf2(sacc[mt][2 * kt][0],     sacc[mt][2 * kt][1]);
                    pf[mt][1] = f2bf2(sacc[mt][2 * kt][2],     sacc[mt][2 * kt][3]);
                    pf[mt][2] = f2bf2(sacc[mt][2 * kt + 1][0], sacc[mt][2 * kt + 1][1]);
                    pf[mt][3] = f2bf2(sacc[mt][2 * kt + 1][2], sacc[mt][2 * kt + 1][3]);
                }
#pragma unroll
                for (int dtp = 0; dtp < 4; ++dtp) {
                    int row = rbase + kt * 16 + (lane & 15);
                    int col = dtp * 16 + ((lane >> 4) & 1) * 8;
                    uint32_t bf[4];
                    ldsm_x4t(bf, uV + (uint32_t)(row * KP + col) * 2);
#pragma unroll
                    for (int mt = 0; mt < 2; ++mt) {
                        mma_bf16(oacc[mt][2 * dtp],     pf[mt], bf[0], bf[1]);
                        mma_bf16(oacc[mt][2 * dtp + 1], pf[mt], bf[2], bf[3]);
                    }
                }
            }
        }
    }

    // l reduction over 4-lane groups
#pragma unroll
    for (int mt = 0; mt < 2; ++mt)
#pragma unroll
        for (int rr = 0; rr < 2; ++rr) {
            lp[mt][rr] += __shfl_xor_sync(0xffffffffu, lp[mt][rr], 1);
            lp[mt][rr] += __shfl_xor_sync(0xffffffffu, lp[mt][rr], 2);
        }

    __nv_bfloat16* Ob = O + (size_t)(b * SS + m0 + wid * 32) * HID + h * HD;
#pragma unroll
    for (int mt = 0; mt < 2; ++mt) {
        const float inv0 = 1.0f / lp[mt][0], inv1 = 1.0f / lp[mt][1];
#pragma unroll
        for (int dt = 0; dt < 8; ++dt) {
            int c = dt * 8 + 2 * t4;
            *(uint32_t*)(Ob + (size_t)(mt * 16 + g) * HID + c) =
                f2bf2(oacc[mt][dt][0] * inv0, oacc[mt][dt][1] * inv0);
            *(uint32_t*)(Ob + (size_t)(mt * 16 + g + 8) * HID + c) =
                f2bf2(oacc[mt][dt][2] * inv1, oacc[mt][dt][3] * inv1);
        }
    }
}

// =============================================================================
// Fused (+bo +x_cls) LayerNorm + partial mean — two-phase, 1 block sync.
// =============================================================================
__global__ __launch_bounds__(256) void ln_mean_kernel(
    const float* __restrict__ O2, const float* __restrict__ x2,
    const float* __restrict__ bo, const float* __restrict__ gamma,
    const float* __restrict__ beta, float* __restrict__ part)
{
    const int blk = blockIdx.x;
    const int b = blk >> 6, slice = blk & 63;
    const int tid = threadIdx.x, lane = tid & 31, wid = tid >> 5;

    __shared__ float smu[16], sinv[16];
    const float* xc = x2 + (size_t)b * SS * HID;
    const int row0 = (b << 10) + (slice << 4);

#pragma unroll
    for (int rr = 0; rr < 2; ++rr) {
        const int t = wid + rr * 8;
        const float* o = O2 + (size_t)(row0 + t) * HID;
        float s = 0.f, ss = 0.f;
#pragma unroll
        for (int k = 0; k < 32; ++k) {
            int j = lane + k * 32;
            float y = o[j] + bo[j] + xc[j];
            s += y; ss += y * y;
        }
#pragma unroll
        for (int off = 16; off; off >>= 1) {
            s  += __shfl_xor_sync(0xffffffffu, s,  off);
            ss += __shfl_xor_sync(0xffffffffu, ss, off);
        }
        if (lane == 0) {
            float mu  = s * (1.0f / HID);
            float var = ss * (1.0f / HID) - mu * mu;
            smu[t]  = mu;
            sinv[t] = rsqrtf(var + 1e-5f);
        }
    }
    __syncthreads();

    float add[4], gam[4], bet[4], acc[4] = {0.f, 0.f, 0.f, 0.f};
#pragma unroll
    for (int it = 0; it < 4; ++it) {
        int j = tid + it * 256;
        add[it] = bo[j] + xc[j];
        gam[it] = gamma[j];
        bet[it] = beta[j];
    }
    for (int t = 0; t < 16; ++t) {
        const float* o = O2 + (size_t)(row0 + t) * HID;
        const float mu = smu[t], inv = sinv[t];
#pragma unroll
        for (int it = 0; it < 4; ++it) {
            float y = o[tid + it * 256] + add[it];
            acc[it] += (y - mu) * inv * gam[it] + bet[it];
        }
    }
#pragma unroll
    for (int it = 0; it < 4; ++it)
        part[(size_t)slice * (BB * HID) + (b << 10) + tid + it * 256] = acc[it];
}

__global__ __launch_bounds__(256) void final_mean_kernel(
    const float* __restrict__ part, float* __restrict__ out)
{
    const int idx = blockIdx.x * 256 + threadIdx.x;
    float s = 0.f;
#pragma unroll
    for (int p = 0; p < 64; ++p) s += part[(size_t)p * (BB * HID) + idx];
    out[idx] = s * (1.0f / SS);
}

// =============================================================================
// launch
// =============================================================================
extern "C" void kernel_launch(void* const* d_in, const int* in_sizes, int n_in,
                              void* d_out, int out_size)
{
    const float* x1    = (const float*)d_in[0];
    const float* x2    = (const float*)d_in[1];
    const int*   mask  = (const int*)  d_in[2];
    const float* Wq    = (const float*)d_in[3];
    const float* Wk    = (const float*)d_in[4];
    const float* Wv    = (const float*)d_in[5];
    const float* Wo    = (const float*)d_in[6];
    const float* bo    = (const float*)d_in[7];
    const float* gamma = (const float*)d_in[8];
    const float* beta  = (const float*)d_in[9];
    float* out = (float*)d_out;

    void *bx1, *bx2, *bw, *bq, *bkv, *bao, *o2, *part;
    cudaGetSymbolAddress(&bx1, g_bx1);
    cudaGetSymbolAddress(&bx2, g_bx2);
    cudaGetSymbolAddress(&bw,  g_bw);
    cudaGetSymbolAddress(&bq,  g_bq);
    cudaGetSymbolAddress(&bkv, g_bkv);
    cudaGetSymbolAddress(&bao, g_bao);
    cudaGetSymbolAddress(&o2,  g_o2);
    cudaGetSymbolAddress(&part, g_part);

    __nv_bfloat16* bW = (__nv_bfloat16*)bw;

    cudaFuncSetAttribute(gemm_qkv,
        cudaFuncAttributeMaxDynamicSharedMemorySize, GEMM_SMEM);
    cudaFuncSetAttribute(gemm_o,
        cudaFuncAttributeMaxDynamicSharedMemorySize, GEMM_SMEM);
    cudaFuncSetAttribute(attn_bf16,
        cudaFuncAttributeMaxDynamicSharedMemorySize, ATT_SMEM);

    // conversions
    dim3 gx(MTOT * HID / 1024, 2);
    conv_x<<<gx, 256>>>(x1, x2, (__nv_bfloat16*)bx1, (__nv_bfloat16*)bx2);
    dim3 gw(HID * HID / 1024, 4);
    conv_w<<<gw, 256>>>(Wq, Wk, Wv, Wo, bW);

    const float QSCALE = 0.125f * 1.4426950408889634f;   // 1/sqrt(64) * log2(e)

    // fused Q + KV projections
    dim3 gqkv(8 + 16, MTOT / TBM);           // (24, 32)
    gemm_qkv<<<gqkv, 128, GEMM_SMEM>>>((const __nv_bfloat16*)bx1,
                                       (const __nv_bfloat16*)bx2,
                                       bW, bW + (size_t)HID * HID,
                                       (__nv_bfloat16*)bq, (__nv_bfloat16*)bkv,
                                       QSCALE);

    dim3 ga(SS / 128, NH, BB);               // (8, 16, 4)
    attn_bf16<<<ga, 128, ATT_SMEM>>>((const __nv_bfloat16*)bq,
                                     (const __nv_bfloat16*)bkv, mask,
                                     (__nv_bfloat16*)bao);

    dim3 go(HID / TBN, MTOT / TBM);          // (8, 32)
    gemm_o<<<go, 128, GEMM_SMEM>>>((const __nv_bfloat16*)bao,
                                   bW + (size_t)3 * HID * HID, (float*)o2);

    ln_mean_kernel<<<BB * 64, 256>>>((const float*)o2, x2, bo, gamma, beta, (float*)part);
    final_mean_kernel<<<BB * HID / 256, 256>>>((const float*)part, out);
}

// round 13
// speedup vs baseline: 1.0193x; 1.0193x over previous
#include <cuda_runtime.h>
#include <cuda_bf16.h>
#include <cstdint>

#define BB   4
#define SS   1024
#define HID  1024
#define NH   16
#define HD   64
#define MTOT (BB*SS)

// ---------------- scratch ----------------
__device__ __nv_bfloat16 g_bx1[MTOT*HID];
__device__ __nv_bfloat16 g_bx2[MTOT*HID];
__device__ __nv_bfloat16 g_bw [4*HID*HID];      // Wq,Wk,Wv,Wo (bf16, contiguous)
__device__ __nv_bfloat16 g_bq [MTOT*HID];
__device__ __nv_bfloat16 g_bkv[MTOT*2*HID];     // fused [K | V] rows, stride 2048
__device__ __nv_bfloat16 g_bao[MTOT*HID];
__device__ float         g_o2 [MTOT*HID];
__device__ float         g_part[64*BB*HID];

// ---------------- helpers ----------------
__device__ __forceinline__ uint32_t f2bf2(float lo, float hi){
    uint32_t r; asm("cvt.rn.bf16x2.f32 %0, %1, %2;" : "=r"(r) : "f"(hi), "f"(lo));
    return r;
}
__device__ __forceinline__ float ex2f(float x){
    float y; asm("ex2.approx.ftz.f32 %0, %1;" : "=f"(y) : "f"(x)); return y;
}
__device__ __forceinline__ void mma_bf16(float* d,
    const uint32_t* a, uint32_t b0, uint32_t b1)
{
    asm volatile(
        "mma.sync.aligned.m16n8k16.row.col.f32.bf16.bf16.f32 "
        "{%0,%1,%2,%3}, {%4,%5,%6,%7}, {%8,%9}, {%0,%1,%2,%3};"
        : "+f"(d[0]), "+f"(d[1]), "+f"(d[2]), "+f"(d[3])
        : "r"(a[0]), "r"(a[1]), "r"(a[2]), "r"(a[3]), "r"(b0), "r"(b1));
}
__device__ __forceinline__ void ldsm_x4(uint32_t* r, uint32_t a){
    asm volatile("ldmatrix.sync.aligned.m8n8.x4.shared.b16 {%0,%1,%2,%3}, [%4];"
                 : "=r"(r[0]), "=r"(r[1]), "=r"(r[2]), "=r"(r[3]) : "r"(a));
}
__device__ __forceinline__ void ldsm_x4t(uint32_t* r, uint32_t a){
    asm volatile("ldmatrix.sync.aligned.m8n8.x4.trans.shared.b16 {%0,%1,%2,%3}, [%4];"
                 : "=r"(r[0]), "=r"(r[1]), "=r"(r[2]), "=r"(r[3]) : "r"(a));
}
__device__ __forceinline__ void cp16(uint32_t dst, const void* src){
    asm volatile("cp.async.cg.shared.global [%0], [%1], 16;" :: "r"(dst), "l"(src));
}
#define CP_COMMIT asm volatile("cp.async.commit_group;" ::: "memory")
#define CP_WAIT1  asm volatile("cp.async.wait_group 1;" ::: "memory")

// =============================================================================
// conversions
// =============================================================================
__global__ __launch_bounds__(256) void conv_x(
    const float* __restrict__ s0, const float* __restrict__ s1,
    __nv_bfloat16* __restrict__ d0, __nv_bfloat16* __restrict__ d1)
{
    const float* s = blockIdx.y ? s1 : s0;
    __nv_bfloat16* d = blockIdx.y ? d1 : d0;
    int i = (blockIdx.x * 256 + threadIdx.x) * 4;
    float4 v = *(const float4*)(s + i);
    *(uint2*)(d + i) = make_uint2(f2bf2(v.x, v.y), f2bf2(v.z, v.w));
}
__global__ __launch_bounds__(256) void conv_w(
    const float* __restrict__ w0, const float* __restrict__ w1,
    const float* __restrict__ w2, const float* __restrict__ w3,
    __nv_bfloat16* __restrict__ d)
{
    const float* s = blockIdx.y == 0 ? w0 : blockIdx.y == 1 ? w1 :
                     blockIdx.y == 2 ? w2 : w3;
    int i = (blockIdx.x * 256 + threadIdx.x) * 4;
    float4 v = *(const float4*)(s + i);
    *(uint2*)(d + (size_t)blockIdx.y * HID * HID + i) =
        make_uint2(f2bf2(v.x, v.y), f2bf2(v.z, v.w));
}

// =============================================================================
// bf16 GEMM core: 128x128x64 CTA tile, 4 warps, warp tile 64x64.
// 3 smem buffers, prefetch distance 2, ONE syncthreads per chunk.
// Fragment double-buffering across k16 steps.
// =============================================================================
#define TBM 128
#define TBN 128
#define TBK 64
#define GPD 72
#define NBUF 3
#define NCH (HID/TBK)                        // 16
#define GEMM_SMEM (NBUF*(TBM+TBN)*GPD*2)     // 110592

__device__ __forceinline__ void gemm_stage(
    const __nv_bfloat16* __restrict__ A, const __nv_bfloat16* __restrict__ W,
    int bm, int bn, int kt, int buf, int tid, uint32_t uBase)
{
    const int k0 = kt * TBK;
    const uint32_t uA = uBase + (uint32_t)buf * TBM * GPD * 2;
    const uint32_t uB = uBase + (uint32_t)(NBUF * TBM + buf * TBN) * GPD * 2;
#pragma unroll
    for (int i = 0; i < 8; ++i) {
        int idx = tid + i * 128;
        int row = idx >> 3, cc = (idx & 7) * 8;
        cp16(uA + (uint32_t)(row * GPD + cc) * 2,
             A + (size_t)(bm + row) * HID + k0 + cc);
        cp16(uB + (uint32_t)(row * GPD + cc) * 2,
             W + (size_t)(bn + row) * HID + k0 + cc);
    }
}

__device__ __forceinline__ void gemm_load_frags(
    uint32_t af[4][4], uint32_t bf[4][4],
    uint32_t uA, uint32_t uB, int kk, int wm, int wn, int lane)
{
#pragma unroll
    for (int mt = 0; mt < 4; ++mt) {
        int row = wm + mt * 16 + (lane & 15);
        int col = kk + ((lane >> 4) << 3);
        ldsm_x4(af[mt], uA + (uint32_t)(row * GPD + col) * 2);
    }
#pragma unroll
    for (int np = 0; np < 4; ++np) {
        int row = wn + np * 16 + ((lane & 16) >> 1) + (lane & 7);
        int col = kk + (lane & 8);
        ldsm_x4(bf[np], uB + (uint32_t)(row * GPD + col) * 2);
    }
}

template<bool OBF>
__device__ __forceinline__ void gemm_core(
    const __nv_bfloat16* __restrict__ A, const __nv_bfloat16* __restrict__ W,
    void* __restrict__ Cv, int ldc, float scale, int bm, int bn, uint32_t uBase)
{
    const int tid = threadIdx.x, lane = tid & 31, wid = tid >> 5;
    const int wm = (wid & 1) * 64, wn = (wid >> 1) * 64;
    const int g = lane >> 2, t4 = lane & 3;

    float acc[4][8][4];
#pragma unroll
    for (int mt = 0; mt < 4; ++mt)
#pragma unroll
        for (int nt = 0; nt < 8; ++nt)
#pragma unroll
            for (int i = 0; i < 4; ++i) acc[mt][nt][i] = 0.f;

#pragma unroll
    for (int p = 0; p < 2; ++p) {
        gemm_stage(A, W, bm, bn, p, p, tid, uBase);
        CP_COMMIT;
    }

    uint32_t af[2][4][4], bf[2][4][4];

    for (int kt = 0; kt < NCH; ++kt) {
        const int buf = kt % NBUF;
        const uint32_t uA = uBase + (uint32_t)buf * TBM * GPD * 2;
        const uint32_t uB = uBase + (uint32_t)(NBUF * TBM + buf * TBN) * GPD * 2;

        CP_WAIT1;
        __syncthreads();

        if (kt + 2 < NCH)
            gemm_stage(A, W, bm, bn, kt + 2, (kt + 2) % NBUF, tid, uBase);
        CP_COMMIT;

        gemm_load_frags(af[0], bf[0], uA, uB, 0, wm, wn, lane);

#pragma unroll
        for (int ks = 0; ks < 4; ++ks) {
            const int cur = ks & 1;
            if (ks < 3)
                gemm_load_frags(af[cur ^ 1], bf[cur ^ 1], uA, uB,
                                (ks + 1) * 16, wm, wn, lane);
#pragma unroll
            for (int mt = 0; mt < 4; ++mt)
#pragma unroll
                for (int np = 0; np < 4; ++np) {
                    mma_bf16(acc[mt][2 * np],     af[cur][mt], bf[cur][np][0], bf[cur][np][1]);
                    mma_bf16(acc[mt][2 * np + 1], af[cur][mt], bf[cur][np][2], bf[cur][np][3]);
                }
        }
    }

    if (OBF) {
        __nv_bfloat16* C = (__nv_bfloat16*)Cv;
#pragma unroll
        for (int mt = 0; mt < 4; ++mt) {
            int r0 = bm + wm + mt * 16 + g;
#pragma unroll
            for (int nt = 0; nt < 8; ++nt) {
                int c = bn + wn + nt * 8 + 2 * t4;
                *(uint32_t*)(C + (size_t)r0 * ldc + c) =
                    f2bf2(acc[mt][nt][0] * scale, acc[mt][nt][1] * scale);
                *(uint32_t*)(C + (size_t)(r0 + 8) * ldc + c) =
                    f2bf2(acc[mt][nt][2] * scale, acc[mt][nt][3] * scale);
            }
        }
    } else {
        float* C = (float*)Cv;
#pragma unroll
        for (int mt = 0; mt < 4; ++mt) {
            int r0 = bm + wm + mt * 16 + g;
#pragma unroll
            for (int nt = 0; nt < 8; ++nt) {
                int c = bn + wn + nt * 8 + 2 * t4;
                *(float2*)(C + (size_t)r0 * ldc + c)       = make_float2(acc[mt][nt][0], acc[mt][nt][1]);
                *(float2*)(C + (size_t)(r0 + 8) * ldc + c) = make_float2(acc[mt][nt][2], acc[mt][nt][3]);
            }
        }
    }
}

// fused Q + KV projection: blockIdx.x < 8 -> Q (x1*Wq, scaled), else KV (x2*Wkv)
__global__ __launch_bounds__(128, 2) void gemm_qkv(
    const __nv_bfloat16* __restrict__ x1, const __nv_bfloat16* __restrict__ x2,
    const __nv_bfloat16* __restrict__ Wq, const __nv_bfloat16* __restrict__ Wkv,
    __nv_bfloat16* __restrict__ Cq, __nv_bfloat16* __restrict__ Ckv, float qscale)
{
    extern __shared__ __nv_bfloat16 smg[];
    const uint32_t uBase = (uint32_t)__cvta_generic_to_shared(smg);
    const int bm = blockIdx.y * TBM;
    if (blockIdx.x < 8) {
        gemm_core<true>(x1, Wq, Cq, HID, qscale, bm, blockIdx.x * TBN, uBase);
    } else {
        gemm_core<true>(x2, Wkv, Ckv, 2 * HID, 1.0f, bm, (blockIdx.x - 8) * TBN, uBase);
    }
}

// O projection (fp32 out)
__global__ __launch_bounds__(128, 2) void gemm_o(
    const __nv_bfloat16* __restrict__ A, const __nv_bfloat16* __restrict__ W,
    float* __restrict__ C)
{
    extern __shared__ __nv_bfloat16 smg[];
    const uint32_t uBase = (uint32_t)__cvta_generic_to_shared(smg);
    gemm_core<false>(A, W, C, HID, 1.0f, blockIdx.y * TBM, blockIdx.x * TBN, uBase);
}

// =============================================================================
// bf16 flash attention: 4 warps x 32 query rows, 64-key tiles, no running max.
// 3 smem buffers, prefetch distance 2, ONE syncthreads per tile.  (R11 config)
// grid (S1/128, H, B)
// =============================================================================
#define ANBUF 3
#define KP 72
#define AKV (64*KP*2)                       // bytes per 64-row tile
#define ATT_SMEM (ANBUF*2*AKV + ANBUF*64*4) // 56064

__device__ __forceinline__ void attn_stage(
    const __nv_bfloat16* __restrict__ Kb, const __nv_bfloat16* __restrict__ Vb,
    const int* __restrict__ mb, int t0, int buf, int tid,
    uint32_t uK, uint32_t uV, float* mskf)
{
#pragma unroll
    for (int i = 0; i < 4; ++i) {
        int idx = tid + i * 128;
        int row = idx >> 3, cc = (idx & 7) * 8;
        cp16(uK + (uint32_t)((buf * 64 + row) * KP + cc) * 2,
             Kb + (size_t)(t0 + row) * 2048 + cc);
        cp16(uV + (uint32_t)((buf * 64 + row) * KP + cc) * 2,
             Vb + (size_t)(t0 + row) * 2048 + cc);
    }
    if (tid < 64) mskf[buf * 64 + tid] = mb[t0 + tid] ? 0.f : -1e9f;
}

__global__ __launch_bounds__(128, 2) void attn_bf16(
    const __nv_bfloat16* __restrict__ Q, const __nv_bfloat16* __restrict__ KVg,
    const int* __restrict__ mask, __nv_bfloat16* __restrict__ O)
{
    extern __shared__ char sma[];
    const uint32_t uK = (uint32_t)__cvta_generic_to_shared(sma);
    const uint32_t uV = uK + ANBUF * AKV;
    float* mskf = (float*)(sma + 2 * ANBUF * AKV);

    const int m0 = blockIdx.x * 128;
    const int h  = blockIdx.y, b = blockIdx.z;
    const int tid = threadIdx.x, lane = tid & 31, wid = tid >> 5;
    const int g = lane >> 2, t4 = lane & 3;

    // Q fragments: 32 rows per warp, 2 m16 tiles
    uint32_t qa[4][2][4];
    const __nv_bfloat16* Qb = Q + (size_t)(b * SS + m0 + wid * 32) * HID + h * HD;
#pragma unroll
    for (int kc = 0; kc < 4; ++kc) {
        int k0 = kc * 16 + t4 * 2;
#pragma unroll
        for (int mt = 0; mt < 2; ++mt) {
            const __nv_bfloat16* Qm = Qb + (size_t)(mt * 16) * HID;
            qa[kc][mt][0] = *(const uint32_t*)(Qm + (size_t)g * HID + k0);
            qa[kc][mt][1] = *(const uint32_t*)(Qm + (size_t)(g + 8) * HID + k0);
            qa[kc][mt][2] = *(const uint32_t*)(Qm + (size_t)g * HID + k0 + 8);
            qa[kc][mt][3] = *(const uint32_t*)(Qm + (size_t)(g + 8) * HID + k0 + 8);
        }
    }

    float oacc[2][8][4];
#pragma unroll
    for (int mt = 0; mt < 2; ++mt)
#pragma unroll
        for (int nt = 0; nt < 8; ++nt)
#pragma unroll
            for (int i = 0; i < 4; ++i) oacc[mt][nt][i] = 0.f;
    float lp[2][2] = {{0.f, 0.f}, {0.f, 0.f}};

    const int* mb = mask + b * SS;
    const __nv_bfloat16* Kb = KVg + (size_t)(b * SS) * 2048 + h * HD;
    const __nv_bfloat16* Vb = Kb + 1024;

#pragma unroll
    for (int p = 0; p < 2; ++p) {
        attn_stage(Kb, Vb, mb, p * 64, p, tid, uK, uV, mskf);
        CP_COMMIT;
    }

    for (int t = 0; t < 16; ++t) {
        const int buf = t % ANBUF;
        CP_WAIT1;
        __syncthreads();

        if (t + 2 < 16)
            attn_stage(Kb, Vb, mb, (t + 2) * 64, (t + 2) % ANBUF, tid, uK, uV, mskf);
        CP_COMMIT;

        // ---- S = Q K^T : per warp 32x64 ----
        float sacc[2][8][4];
#pragma unroll
        for (int mt = 0; mt < 2; ++mt)
#pragma unroll
            for (int nt = 0; nt < 8; ++nt)
#pragma unroll
                for (int i = 0; i < 4; ++i) sacc[mt][nt][i] = 0.f;
#pragma unroll
        for (int ks = 0; ks < 4; ++ks) {
            const int kk = ks * 16;
#pragma unroll
            for (int np = 0; np < 4; ++np) {
                int row = buf * 64 + np * 16 + ((lane & 16) >> 1) + (lane & 7);
                int col = kk + (lane & 8);
                uint32_t bfr[4];
                ldsm_x4(bfr, uK + (uint32_t)(row * KP + col) * 2);
#pragma unroll
                for (int mt = 0; mt < 2; ++mt) {
                    mma_bf16(sacc[mt][2 * np],     qa[ks][mt], bfr[0], bfr[1]);
                    mma_bf16(sacc[mt][2 * np + 1], qa[ks][mt], bfr[2], bfr[3]);
                }
            }
        }

        // ---- p = exp2(s + mask) ----
#pragma unroll
        for (int mt = 0; mt < 2; ++mt)
#pragma unroll
            for (int nt = 0; nt < 8; ++nt) {
                int c = nt * 8 + 2 * t4;
                float a0 = mskf[buf * 64 + c], a1 = mskf[buf * 64 + c + 1];
                sacc[mt][nt][0] = ex2f(sacc[mt][nt][0] + a0);
                sacc[mt][nt][1] = ex2f(sacc[mt][nt][1] + a1);
                sacc[mt][nt][2] = ex2f(sacc[mt][nt][2] + a0);
                sacc[mt][nt][3] = ex2f(sacc[mt][nt][3] + a1);
                lp[mt][0] += sacc[mt][nt][0] + sacc[mt][nt][1];
                lp[mt][1] += sacc[mt][nt][2] + sacc[mt][nt][3];
            }

        // ---- O += P V (P in registers) ----
#pragma unroll
        for (int kt = 0; kt < 4; ++kt) {
            uint32_t pf[2][4];
#pragma unroll
            for (int mt = 0; mt < 2; ++mt) {
                pf[mt][0] = f2bf2(sacc[mt][2 * kt][0],     sacc[mt][2 * kt][1]);
                pf[mt][1] = f2bf2(sacc[mt][2 * kt][2],     sacc[mt][2 * kt][3]);
                pf[mt][2] = f2bf2(sacc[mt][2 * kt + 1][0], sacc[mt][2 * kt + 1][1]);
                pf[mt][3] = f2bf2(sacc[mt][2 * kt + 1][2], sacc[mt][2 * kt + 1][3]);
            }
#pragma unroll
            for (int dtp = 0; dtp < 4; ++dtp) {
                int row = buf * 64 + kt * 16 + (lane & 15);
                int col = dtp * 16 + ((lane >> 4) & 1) * 8;
                uint32_t bfr[4];
                ldsm_x4t(bfr, uV + (uint32_t)(row * KP + col) * 2);
#pragma unroll
                for (int mt = 0; mt < 2; ++mt) {
                    mma_bf16(oacc[mt][2 * dtp],     pf[mt], bfr[0], bfr[1]);
                    mma_bf16(oacc[mt][2 * dtp + 1], pf[mt], bfr[2], bfr[3]);
                }
            }
        }
    }

    // l reduction over 4-lane groups
#pragma unroll
    for (int mt = 0; mt < 2; ++mt)
#pragma unroll
        for (int rr = 0; rr < 2; ++rr) {
            lp[mt][rr] += __shfl_xor_sync(0xffffffffu, lp[mt][rr], 1);
            lp[mt][rr] += __shfl_xor_sync(0xffffffffu, lp[mt][rr], 2);
        }

    __nv_bfloat16* Ob = O + (size_t)(b * SS + m0 + wid * 32) * HID + h * HD;
#pragma unroll
    for (int mt = 0; mt < 2; ++mt) {
        const float inv0 = 1.0f / lp[mt][0], inv1 = 1.0f / lp[mt][1];
#pragma unroll
        for (int dt = 0; dt < 8; ++dt) {
            int c = dt * 8 + 2 * t4;
            *(uint32_t*)(Ob + (size_t)(mt * 16 + g) * HID + c) =
                f2bf2(oacc[mt][dt][0] * inv0, oacc[mt][dt][1] * inv0);
            *(uint32_t*)(Ob + (size_t)(mt * 16 + g + 8) * HID + c) =
                f2bf2(oacc[mt][dt][2] * inv1, oacc[mt][dt][3] * inv1);
        }
    }
}

// =============================================================================
// Fused (+bo +x_cls) LayerNorm + partial mean — two-phase, 1 block sync.
// =============================================================================
__global__ __launch_bounds__(256) void ln_mean_kernel(
    const float* __restrict__ O2, const float* __restrict__ x2,
    const float* __restrict__ bo, const float* __restrict__ gamma,
    const float* __restrict__ beta, float* __restrict__ part)
{
    const int blk = blockIdx.x;
    const int b = blk >> 6, slice = blk & 63;
    const int tid = threadIdx.x, lane = tid & 31, wid = tid >> 5;

    __shared__ float smu[16], sinv[16];
    const float* xc = x2 + (size_t)b * SS * HID;
    const int row0 = (b << 10) + (slice << 4);

#pragma unroll
    for (int rr = 0; rr < 2; ++rr) {
        const int t = wid + rr * 8;
        const float* o = O2 + (size_t)(row0 + t) * HID;
        float s = 0.f, ss = 0.f;
#pragma unroll
        for (int k = 0; k < 32; ++k) {
            int j = lane + k * 32;
            float y = o[j] + bo[j] + xc[j];
            s += y; ss += y * y;
        }
#pragma unroll
        for (int off = 16; off; off >>= 1) {
            s  += __shfl_xor_sync(0xffffffffu, s,  off);
            ss += __shfl_xor_sync(0xffffffffu, ss, off);
        }
        if (lane == 0) {
            float mu  = s * (1.0f / HID);
            float var = ss * (1.0f / HID) - mu * mu;
            smu[t]  = mu;
            sinv[t] = rsqrtf(var + 1e-5f);
        }
    }
    __syncthreads();

    float add[4], gam[4], bet[4], acc[4] = {0.f, 0.f, 0.f, 0.f};
#pragma unroll
    for (int it = 0; it < 4; ++it) {
        int j = tid + it * 256;
        add[it] = bo[j] + xc[j];
        gam[it] = gamma[j];
        bet[it] = beta[j];
    }
    for (int t = 0; t < 16; ++t) {
        const float* o = O2 + (size_t)(row0 + t) * HID;
        const float mu = smu[t], inv = sinv[t];
#pragma unroll
        for (int it = 0; it < 4; ++it) {
            float y = o[tid + it * 256] + add[it];
            acc[it] += (y - mu) * inv * gam[it] + bet[it];
        }
    }
#pragma unroll
    for (int it = 0; it < 4; ++it)
        part[(size_t)slice * (BB * HID) + (b << 10) + tid + it * 256] = acc[it];
}

__global__ __launch_bounds__(256) void final_mean_kernel(
    const float* __restrict__ part, float* __restrict__ out)
{
    const int idx = blockIdx.x * 256 + threadIdx.x;
    float s = 0.f;
#pragma unroll
    for (int p = 0; p < 64; ++p) s += part[(size_t)p * (BB * HID) + idx];
    out[idx] = s * (1.0f / SS);
}

// =============================================================================
// launch
// =============================================================================
extern "C" void kernel_launch(void* const* d_in, const int* in_sizes, int n_in,
                              void* d_out, int out_size)
{
    const float* x1    = (const float*)d_in[0];
    const float* x2    = (const float*)d_in[1];
    const int*   mask  = (const int*)  d_in[2];
    const float* Wq    = (const float*)d_in[3];
    const float* Wk    = (const float*)d_in[4];
    const float* Wv    = (const float*)d_in[5];
    const float* Wo    = (const float*)d_in[6];
    const float* bo    = (const float*)d_in[7];
    const float* gamma = (const float*)d_in[8];
    const float* beta  = (const float*)d_in[9];
    float* out = (float*)d_out;

    void *bx1, *bx2, *bw, *bq, *bkv, *bao, *o2, *part;
    cudaGetSymbolAddress(&bx1, g_bx1);
    cudaGetSymbolAddress(&bx2, g_bx2);
    cudaGetSymbolAddress(&bw,  g_bw);
    cudaGetSymbolAddress(&bq,  g_bq);
    cudaGetSymbolAddress(&bkv, g_bkv);
    cudaGetSymbolAddress(&bao, g_bao);
    cudaGetSymbolAddress(&o2,  g_o2);
    cudaGetSymbolAddress(&part, g_part);

    __nv_bfloat16* bW = (__nv_bfloat16*)bw;

    cudaFuncSetAttribute(gemm_qkv,
        cudaFuncAttributeMaxDynamicSharedMemorySize, GEMM_SMEM);
    cudaFuncSetAttribute(gemm_o,
        cudaFuncAttributeMaxDynamicSharedMemorySize, GEMM_SMEM);
    cudaFuncSetAttribute(attn_bf16,
        cudaFuncAttributeMaxDynamicSharedMemorySize, ATT_SMEM);

    // conversions
    dim3 gx(MTOT * HID / 1024, 2);
    conv_x<<<gx, 256>>>(x1, x2, (__nv_bfloat16*)bx1, (__nv_bfloat16*)bx2);
    dim3 gw(HID * HID / 1024, 4);
    conv_w<<<gw, 256>>>(Wq, Wk, Wv, Wo, bW);

    const float QSCALE = 0.125f * 1.4426950408889634f;   // 1/sqrt(64) * log2(e)

    // fused Q + KV projections
    dim3 gqkv(8 + 16, MTOT / TBM);           // (24, 32)
    gemm_qkv<<<gqkv, 128, GEMM_SMEM>>>((const __nv_bfloat16*)bx1,
                                       (const __nv_bfloat16*)bx2,
                                       bW, bW + (size_t)HID * HID,
                                       (__nv_bfloat16*)bq, (__nv_bfloat16*)bkv,
                                       QSCALE);

    dim3 ga(SS / 128, NH, BB);               // (8, 16, 4)
    attn_bf16<<<ga, 128, ATT_SMEM>>>((const __nv_bfloat16*)bq,
                                     (const __nv_bfloat16*)bkv, mask,
                                     (__nv_bfloat16*)bao);

    dim3 go(HID / TBN, MTOT / TBM);          // (8, 32)
    gemm_o<<<go, 128, GEMM_SMEM>>>((const __nv_bfloat16*)bao,
                                   bW + (size_t)3 * HID * HID, (float*)o2);

    ln_mean_kernel<<<BB * 64, 256>>>((const float*)o2, x2, bo, gamma, beta, (float*)part);
    final_mean_kernel<<<BB * HID / 256, 256>>>((const float*)part, out);
}

// round 14
// speedup vs baseline: 1.1168x; 1.0957x over previous
#include <cuda_runtime.h>
#include <cuda_bf16.h>
#include <cstdint>

#define BB   4
#define SS   1024
#define HID  1024
#define NH   16
#define HD   64
#define MTOT (BB*SS)

// ---------------- scratch ----------------
__device__ __nv_bfloat16 g_bx1[MTOT*HID];
__device__ __nv_bfloat16 g_bx2[MTOT*HID];
__device__ __nv_bfloat16 g_bw [4*HID*HID];      // Wq,Wk,Wv,Wo (bf16, contiguous)
__device__ __nv_bfloat16 g_bq [MTOT*HID];
__device__ __nv_bfloat16 g_bkv[MTOT*2*HID];     // fused [K | V] rows, stride 2048
__device__ __nv_bfloat16 g_bao[MTOT*HID];
__device__ float         g_o2 [MTOT*HID];
__device__ float         g_part[64*BB*HID];
__device__ int           g_idx [BB*SS];         // compacted key indices
__device__ float         g_amask[BB*SS];        // 0 for kept, -1e9 for pad
__device__ int           g_cnt [BB];            // 64-key tile count per batch

// ---------------- helpers ----------------
__device__ __forceinline__ uint32_t f2bf2(float lo, float hi){
    uint32_t r; asm("cvt.rn.bf16x2.f32 %0, %1, %2;" : "=r"(r) : "f"(hi), "f"(lo));
    return r;
}
__device__ __forceinline__ float ex2f(float x){
    float y; asm("ex2.approx.ftz.f32 %0, %1;" : "=f"(y) : "f"(x)); return y;
}
__device__ __forceinline__ void mma_bf16(float* d,
    const uint32_t* a, uint32_t b0, uint32_t b1)
{
    asm volatile(
        "mma.sync.aligned.m16n8k16.row.col.f32.bf16.bf16.f32 "
        "{%0,%1,%2,%3}, {%4,%5,%6,%7}, {%8,%9}, {%0,%1,%2,%3};"
        : "+f"(d[0]), "+f"(d[1]), "+f"(d[2]), "+f"(d[3])
        : "r"(a[0]), "r"(a[1]), "r"(a[2]), "r"(a[3]), "r"(b0), "r"(b1));
}
__device__ __forceinline__ void ldsm_x4(uint32_t* r, uint32_t a){
    asm volatile("ldmatrix.sync.aligned.m8n8.x4.shared.b16 {%0,%1,%2,%3}, [%4];"
                 : "=r"(r[0]), "=r"(r[1]), "=r"(r[2]), "=r"(r[3]) : "r"(a));
}
__device__ __forceinline__ void ldsm_x4t(uint32_t* r, uint32_t a){
    asm volatile("ldmatrix.sync.aligned.m8n8.x4.trans.shared.b16 {%0,%1,%2,%3}, [%4];"
                 : "=r"(r[0]), "=r"(r[1]), "=r"(r[2]), "=r"(r[3]) : "r"(a));
}
__device__ __forceinline__ void cp16(uint32_t dst, const void* src){
    asm volatile("cp.async.cg.shared.global [%0], [%1], 16;" :: "r"(dst), "l"(src));
}
#define CP_COMMIT asm volatile("cp.async.commit_group;" ::: "memory")
#define CP_WAIT1  asm volatile("cp.async.wait_group 1;" ::: "memory")

// =============================================================================
// conversions
// =============================================================================
__global__ __launch_bounds__(256) void conv_x(
    const float* __restrict__ s0, const float* __restrict__ s1,
    __nv_bfloat16* __restrict__ d0, __nv_bfloat16* __restrict__ d1)
{
    const float* s = blockIdx.y ? s1 : s0;
    __nv_bfloat16* d = blockIdx.y ? d1 : d0;
    int i = (blockIdx.x * 256 + threadIdx.x) * 4;
    float4 v = *(const float4*)(s + i);
    *(uint2*)(d + i) = make_uint2(f2bf2(v.x, v.y), f2bf2(v.z, v.w));
}
__global__ __launch_bounds__(256) void conv_w(
    const float* __restrict__ w0, const float* __restrict__ w1,
    const float* __restrict__ w2, const float* __restrict__ w3,
    __nv_bfloat16* __restrict__ d)
{
    const float* s = blockIdx.y == 0 ? w0 : blockIdx.y == 1 ? w1 :
                     blockIdx.y == 2 ? w2 : w3;
    int i = (blockIdx.x * 256 + threadIdx.x) * 4;
    float4 v = *(const float4*)(s + i);
    *(uint2*)(d + (size_t)blockIdx.y * HID * HID + i) =
        make_uint2(f2bf2(v.x, v.y), f2bf2(v.z, v.w));
}

// =============================================================================
// mask compaction: per batch, list of kept key indices, padded to 64-multiple.
// Deterministic (stable order). grid = BB blocks x 256 threads.
// =============================================================================
__global__ __launch_bounds__(256) void compact_mask(const int* __restrict__ mask)
{
    const int b = blockIdx.x;
    const int tid = threadIdx.x, lane = tid & 31, wid = tid >> 5;
    __shared__ int wsum[8];

    int m[4], cnt = 0;
    const int base = b * SS + tid * 4;
#pragma unroll
    for (int i = 0; i < 4; ++i) { m[i] = mask[base + i]; cnt += (m[i] != 0); }

    // inclusive warp scan of per-thread counts
    int pre = cnt;
#pragma unroll
    for (int off = 1; off < 32; off <<= 1) {
        int v = __shfl_up_sync(0xffffffffu, pre, off);
        if (lane >= off) pre += v;
    }
    if (lane == 31) wsum[wid] = pre;
    __syncthreads();

    int wbase = 0;
#pragma unroll
    for (int w = 0; w < 8; ++w) if (w < wid) wbase += wsum[w];
    int pos = wbase + pre - cnt;            // exclusive prefix

#pragma unroll
    for (int i = 0; i < 4; ++i) {
        if (m[i]) {
            g_idx[b * SS + pos]   = tid * 4 + i;
            g_amask[b * SS + pos] = 0.f;
            ++pos;
        }
    }

    int total = 0;
#pragma unroll
    for (int w = 0; w < 8; ++w) total += wsum[w];
    const int padded = (total + 63) & ~63;
    for (int j = total + tid; j < padded; j += 256) {
        g_idx[b * SS + j]   = 0;
        g_amask[b * SS + j] = -1e9f;
    }
    if (tid == 0) g_cnt[b] = padded >> 6;
}

// =============================================================================
// bf16 GEMM core: 128x128x64 CTA tile, 4 warps, warp tile 64x64.
// 3 smem buffers, prefetch distance 2, ONE syncthreads per chunk.
// =============================================================================
#define TBM 128
#define TBN 128
#define TBK 64
#define GPD 72
#define NBUF 3
#define NCH (HID/TBK)                        // 16
#define GEMM_SMEM (NBUF*(TBM+TBN)*GPD*2)     // 110592

__device__ __forceinline__ void gemm_stage(
    const __nv_bfloat16* __restrict__ A, const __nv_bfloat16* __restrict__ W,
    int bm, int bn, int kt, int buf, int tid, uint32_t uBase)
{
    const int k0 = kt * TBK;
    const uint32_t uA = uBase + (uint32_t)buf * TBM * GPD * 2;
    const uint32_t uB = uBase + (uint32_t)(NBUF * TBM + buf * TBN) * GPD * 2;
#pragma unroll
    for (int i = 0; i < 8; ++i) {
        int idx = tid + i * 128;
        int row = idx >> 3, cc = (idx & 7) * 8;
        cp16(uA + (uint32_t)(row * GPD + cc) * 2,
             A + (size_t)(bm + row) * HID + k0 + cc);
        cp16(uB + (uint32_t)(row * GPD + cc) * 2,
             W + (size_t)(bn + row) * HID + k0 + cc);
    }
}

__device__ __forceinline__ void gemm_load_frags(
    uint32_t af[4][4], uint32_t bf[4][4],
    uint32_t uA, uint32_t uB, int kk, int wm, int wn, int lane)
{
#pragma unroll
    for (int mt = 0; mt < 4; ++mt) {
        int row = wm + mt * 16 + (lane & 15);
        int col = kk + ((lane >> 4) << 3);
        ldsm_x4(af[mt], uA + (uint32_t)(row * GPD + col) * 2);
    }
#pragma unroll
    for (int np = 0; np < 4; ++np) {
        int row = wn + np * 16 + ((lane & 16) >> 1) + (lane & 7);
        int col = kk + (lane & 8);
        ldsm_x4(bf[np], uB + (uint32_t)(row * GPD + col) * 2);
    }
}

template<bool OBF>
__device__ __forceinline__ void gemm_core(
    const __nv_bfloat16* __restrict__ A, const __nv_bfloat16* __restrict__ W,
    void* __restrict__ Cv, int ldc, float scale, int bm, int bn, uint32_t uBase)
{
    const int tid = threadIdx.x, lane = tid & 31, wid = tid >> 5;
    const int wm = (wid & 1) * 64, wn = (wid >> 1) * 64;
    const int g = lane >> 2, t4 = lane & 3;

    float acc[4][8][4];
#pragma unroll
    for (int mt = 0; mt < 4; ++mt)
#pragma unroll
        for (int nt = 0; nt < 8; ++nt)
#pragma unroll
            for (int i = 0; i < 4; ++i) acc[mt][nt][i] = 0.f;

#pragma unroll
    for (int p = 0; p < 2; ++p) {
        gemm_stage(A, W, bm, bn, p, p, tid, uBase);
        CP_COMMIT;
    }

    uint32_t af[2][4][4], bf[2][4][4];

    for (int kt = 0; kt < NCH; ++kt) {
        const int buf = kt % NBUF;
        const uint32_t uA = uBase + (uint32_t)buf * TBM * GPD * 2;
        const uint32_t uB = uBase + (uint32_t)(NBUF * TBM + buf * TBN) * GPD * 2;

        CP_WAIT1;
        __syncthreads();

        if (kt + 2 < NCH)
            gemm_stage(A, W, bm, bn, kt + 2, (kt + 2) % NBUF, tid, uBase);
        CP_COMMIT;

        gemm_load_frags(af[0], bf[0], uA, uB, 0, wm, wn, lane);

#pragma unroll
        for (int ks = 0; ks < 4; ++ks) {
            const int cur = ks & 1;
            if (ks < 3)
                gemm_load_frags(af[cur ^ 1], bf[cur ^ 1], uA, uB,
                                (ks + 1) * 16, wm, wn, lane);
#pragma unroll
            for (int mt = 0; mt < 4; ++mt)
#pragma unroll
                for (int np = 0; np < 4; ++np) {
                    mma_bf16(acc[mt][2 * np],     af[cur][mt], bf[cur][np][0], bf[cur][np][1]);
                    mma_bf16(acc[mt][2 * np + 1], af[cur][mt], bf[cur][np][2], bf[cur][np][3]);
                }
        }
    }

    if (OBF) {
        __nv_bfloat16* C = (__nv_bfloat16*)Cv;
#pragma unroll
        for (int mt = 0; mt < 4; ++mt) {
            int r0 = bm + wm + mt * 16 + g;
#pragma unroll
            for (int nt = 0; nt < 8; ++nt) {
                int c = bn + wn + nt * 8 + 2 * t4;
                *(uint32_t*)(C + (size_t)r0 * ldc + c) =
                    f2bf2(acc[mt][nt][0] * scale, acc[mt][nt][1] * scale);
                *(uint32_t*)(C + (size_t)(r0 + 8) * ldc + c) =
                    f2bf2(acc[mt][nt][2] * scale, acc[mt][nt][3] * scale);
            }
        }
    } else {
        float* C = (float*)Cv;
#pragma unroll
        for (int mt = 0; mt < 4; ++mt) {
            int r0 = bm + wm + mt * 16 + g;
#pragma unroll
            for (int nt = 0; nt < 8; ++nt) {
                int c = bn + wn + nt * 8 + 2 * t4;
                *(float2*)(C + (size_t)r0 * ldc + c)       = make_float2(acc[mt][nt][0], acc[mt][nt][1]);
                *(float2*)(C + (size_t)(r0 + 8) * ldc + c) = make_float2(acc[mt][nt][2], acc[mt][nt][3]);
            }
        }
    }
}

// fused Q + KV projection: blockIdx.x < 8 -> Q (x1*Wq, scaled), else KV (x2*Wkv)
__global__ __launch_bounds__(128, 2) void gemm_qkv(
    const __nv_bfloat16* __restrict__ x1, const __nv_bfloat16* __restrict__ x2,
    const __nv_bfloat16* __restrict__ Wq, const __nv_bfloat16* __restrict__ Wkv,
    __nv_bfloat16* __restrict__ Cq, __nv_bfloat16* __restrict__ Ckv, float qscale)
{
    extern __shared__ __nv_bfloat16 smg[];
    const uint32_t uBase = (uint32_t)__cvta_generic_to_shared(smg);
    const int bm = blockIdx.y * TBM;
    if (blockIdx.x < 8) {
        gemm_core<true>(x1, Wq, Cq, HID, qscale, bm, blockIdx.x * TBN, uBase);
    } else {
        gemm_core<true>(x2, Wkv, Ckv, 2 * HID, 1.0f, bm, (blockIdx.x - 8) * TBN, uBase);
    }
}

// O projection (fp32 out)
__global__ __launch_bounds__(128, 2) void gemm_o(
    const __nv_bfloat16* __restrict__ A, const __nv_bfloat16* __restrict__ W,
    float* __restrict__ C)
{
    extern __shared__ __nv_bfloat16 smg[];
    const uint32_t uBase = (uint32_t)__cvta_generic_to_shared(smg);
    gemm_core<false>(A, W, C, HID, 1.0f, blockIdx.y * TBM, blockIdx.x * TBN, uBase);
}

// =============================================================================
// bf16 flash attention with COMPACTED keys: only unmasked keys are processed
// (masked keys contribute exactly 0). 4 warps x 32 query rows, 64-key tiles,
// 3 smem buffers, 1 sync per tile. grid (S1/128, H, B)
// =============================================================================
#define ANBUF 3
#define KP 72
#define AKV (64*KP*2)                       // bytes per 64-row tile
#define ATT_SMEM (ANBUF*2*AKV + ANBUF*64*4) // 56064

__device__ __forceinline__ void attn_stage(
    const __nv_bfloat16* __restrict__ Kb, const __nv_bfloat16* __restrict__ Vb,
    const int* __restrict__ ibase, const float* __restrict__ abase,
    int t0, int buf, int tid, uint32_t uK, uint32_t uV, float* mskf)
{
#pragma unroll
    for (int i = 0; i < 4; ++i) {
        int idx = tid + i * 128;
        int row = idx >> 3, cc = (idx & 7) * 8;
        const int rs = ibase[t0 + row];
        cp16(uK + (uint32_t)((buf * 64 + row) * KP + cc) * 2,
             Kb + (size_t)rs * 2048 + cc);
        cp16(uV + (uint32_t)((buf * 64 + row) * KP + cc) * 2,
             Vb + (size_t)rs * 2048 + cc);
    }
    if (tid < 64) mskf[buf * 64 + tid] = abase[t0 + tid];
}

__global__ __launch_bounds__(128, 2) void attn_bf16(
    const __nv_bfloat16* __restrict__ Q, const __nv_bfloat16* __restrict__ KVg,
    __nv_bfloat16* __restrict__ O)
{
    extern __shared__ char sma[];
    const uint32_t uK = (uint32_t)__cvta_generic_to_shared(sma);
    const uint32_t uV = uK + ANBUF * AKV;
    float* mskf = (float*)(sma + 2 * ANBUF * AKV);

    const int m0 = blockIdx.x * 128;
    const int h  = blockIdx.y, b = blockIdx.z;
    const int tid = threadIdx.x, lane = tid & 31, wid = tid >> 5;
    const int g = lane >> 2, t4 = lane & 3;

    const int ntiles = g_cnt[b];
    const int*   ibase = g_idx   + b * SS;
    const float* abase = g_amask + b * SS;

    // Q fragments: 32 rows per warp, 2 m16 tiles
    uint32_t qa[4][2][4];
    const __nv_bfloat16* Qb = Q + (size_t)(b * SS + m0 + wid * 32) * HID + h * HD;
#pragma unroll
    for (int kc = 0; kc < 4; ++kc) {
        int k0 = kc * 16 + t4 * 2;
#pragma unroll
        for (int mt = 0; mt < 2; ++mt) {
            const __nv_bfloat16* Qm = Qb + (size_t)(mt * 16) * HID;
            qa[kc][mt][0] = *(const uint32_t*)(Qm + (size_t)g * HID + k0);
            qa[kc][mt][1] = *(const uint32_t*)(Qm + (size_t)(g + 8) * HID + k0);
            qa[kc][mt][2] = *(const uint32_t*)(Qm + (size_t)g * HID + k0 + 8);
            qa[kc][mt][3] = *(const uint32_t*)(Qm + (size_t)(g + 8) * HID + k0 + 8);
        }
    }

    float oacc[2][8][4];
#pragma unroll
    for (int mt = 0; mt < 2; ++mt)
#pragma unroll
        for (int nt = 0; nt < 8; ++nt)
#pragma unroll
            for (int i = 0; i < 4; ++i) oacc[mt][nt][i] = 0.f;
    float lp[2][2] = {{0.f, 0.f}, {0.f, 0.f}};

    const __nv_bfloat16* Kb = KVg + (size_t)(b * SS) * 2048 + h * HD;
    const __nv_bfloat16* Vb = Kb + 1024;

    for (int p = 0; p < 2 && p < ntiles; ++p) {
        attn_stage(Kb, Vb, ibase, abase, p * 64, p, tid, uK, uV, mskf);
        CP_COMMIT;
    }

    for (int t = 0; t < ntiles; ++t) {
        const int buf = t % ANBUF;
        CP_WAIT1;
        __syncthreads();

        if (t + 2 < ntiles)
            attn_stage(Kb, Vb, ibase, abase, (t + 2) * 64, (t + 2) % ANBUF,
                       tid, uK, uV, mskf);
        CP_COMMIT;

        // ---- S = Q K^T : per warp 32x64 ----
        float sacc[2][8][4];
#pragma unroll
        for (int mt = 0; mt < 2; ++mt)
#pragma unroll
            for (int nt = 0; nt < 8; ++nt)
#pragma unroll
                for (int i = 0; i < 4; ++i) sacc[mt][nt][i] = 0.f;
#pragma unroll
        for (int ks = 0; ks < 4; ++ks) {
            const int kk = ks * 16;
#pragma unroll
            for (int np = 0; np < 4; ++np) {
                int row = buf * 64 + np * 16 + ((lane & 16) >> 1) + (lane & 7);
                int col = kk + (lane & 8);
                uint32_t bfr[4];
                ldsm_x4(bfr, uK + (uint32_t)(row * KP + col) * 2);
#pragma unroll
                for (int mt = 0; mt < 2; ++mt) {
                    mma_bf16(sacc[mt][2 * np],     qa[ks][mt], bfr[0], bfr[1]);
                    mma_bf16(sacc[mt][2 * np + 1], qa[ks][mt], bfr[2], bfr[3]);
                }
            }
        }

        // ---- p = exp2(s + amask) ----
#pragma unroll
        for (int mt = 0; mt < 2; ++mt)
#pragma unroll
            for (int nt = 0; nt < 8; ++nt) {
                int c = nt * 8 + 2 * t4;
                float a0 = mskf[buf * 64 + c], a1 = mskf[buf * 64 + c + 1];
                sacc[mt][nt][0] = ex2f(sacc[mt][nt][0] + a0);
                sacc[mt][nt][1] = ex2f(sacc[mt][nt][1] + a1);
                sacc[mt][nt][2] = ex2f(sacc[mt][nt][2] + a0);
                sacc[mt][nt][3] = ex2f(sacc[mt][nt][3] + a1);
                lp[mt][0] += sacc[mt][nt][0] + sacc[mt][nt][1];
                lp[mt][1] += sacc[mt][nt][2] + sacc[mt][nt][3];
            }

        // ---- O += P V (P in registers) ----
#pragma unroll
        for (int kt = 0; kt < 4; ++kt) {
            uint32_t pf[2][4];
#pragma unroll
            for (int mt = 0; mt < 2; ++mt) {
                pf[mt][0] = f2bf2(sacc[mt][2 * kt][0],     sacc[mt][2 * kt][1]);
                pf[mt][1] = f2bf2(sacc[mt][2 * kt][2],     sacc[mt][2 * kt][3]);
                pf[mt][2] = f2bf2(sacc[mt][2 * kt + 1][0], sacc[mt][2 * kt + 1][1]);
                pf[mt][3] = f2bf2(sacc[mt][2 * kt + 1][2], sacc[mt][2 * kt + 1][3]);
            }
#pragma unroll
            for (int dtp = 0; dtp < 4; ++dtp) {
                int row = buf * 64 + kt * 16 + (lane & 15);
                int col = dtp * 16 + ((lane >> 4) & 1) * 8;
                uint32_t bfr[4];
                ldsm_x4t(bfr, uV + (uint32_t)(row * KP + col) * 2);
#pragma unroll
                for (int mt = 0; mt < 2; ++mt) {
                    mma_bf16(oacc[mt][2 * dtp],     pf[mt], bfr[0], bfr[1]);
                    mma_bf16(oacc[mt][2 * dtp + 1], pf[mt], bfr[2], bfr[3]);
                }
            }
        }
    }

    // l reduction over 4-lane groups
#pragma unroll
    for (int mt = 0; mt < 2; ++mt)
#pragma unroll
        for (int rr = 0; rr < 2; ++rr) {
            lp[mt][rr] += __shfl_xor_sync(0xffffffffu, lp[mt][rr], 1);
            lp[mt][rr] += __shfl_xor_sync(0xffffffffu, lp[mt][rr], 2);
        }

    __nv_bfloat16* Ob = O + (size_t)(b * SS + m0 + wid * 32) * HID + h * HD;
#pragma unroll
    for (int mt = 0; mt < 2; ++mt) {
        const float inv0 = 1.0f / lp[mt][0], inv1 = 1.0f / lp[mt][1];
#pragma unroll
        for (int dt = 0; dt < 8; ++dt) {
            int c = dt * 8 + 2 * t4;
            *(uint32_t*)(Ob + (size_t)(mt * 16 + g) * HID + c) =
                f2bf2(oacc[mt][dt][0] * inv0, oacc[mt][dt][1] * inv0);
            *(uint32_t*)(Ob + (size_t)(mt * 16 + g + 8) * HID + c) =
                f2bf2(oacc[mt][dt][2] * inv1, oacc[mt][dt][3] * inv1);
        }
    }
}

// =============================================================================
// Fused (+bo +x_cls) LayerNorm + partial mean — two-phase, 1 block sync.
// =============================================================================
__global__ __launch_bounds__(256) void ln_mean_kernel(
    const float* __restrict__ O2, const float* __restrict__ x2,
    const float* __restrict__ bo, const float* __restrict__ gamma,
    const float* __restrict__ beta, float* __restrict__ part)
{
    const int blk = blockIdx.x;
    const int b = blk >> 6, slice = blk & 63;
    const int tid = threadIdx.x, lane = tid & 31, wid = tid >> 5;

    __shared__ float smu[16], sinv[16];
    const float* xc = x2 + (size_t)b * SS * HID;
    const int row0 = (b << 10) + (slice << 4);

#pragma unroll
    for (int rr = 0; rr < 2; ++rr) {
        const int t = wid + rr * 8;
        const float* o = O2 + (size_t)(row0 + t) * HID;
        float s = 0.f, ss = 0.f;
#pragma unroll
        for (int k = 0; k < 32; ++k) {
            int j = lane + k * 32;
            float y = o[j] + bo[j] + xc[j];
            s += y; ss += y * y;
        }
#pragma unroll
        for (int off = 16; off; off >>= 1) {
            s  += __shfl_xor_sync(0xffffffffu, s,  off);
            ss += __shfl_xor_sync(0xffffffffu, ss, off);
        }
        if (lane == 0) {
            float mu  = s * (1.0f / HID);
            float var = ss * (1.0f / HID) - mu * mu;
            smu[t]  = mu;
            sinv[t] = rsqrtf(var + 1e-5f);
        }
    }
    __syncthreads();

    float add[4], gam[4], bet[4], acc[4] = {0.f, 0.f, 0.f, 0.f};
#pragma unroll
    for (int it = 0; it < 4; ++it) {
        int j = tid + it * 256;
        add[it] = bo[j] + xc[j];
        gam[it] = gamma[j];
        bet[it] = beta[j];
    }
    for (int t = 0; t < 16; ++t) {
        const float* o = O2 + (size_t)(row0 + t) * HID;
        const float mu = smu[t], inv = sinv[t];
#pragma unroll
        for (int it = 0; it < 4; ++it) {
            float y = o[tid + it * 256] + add[it];
            acc[it] += (y - mu) * inv * gam[it] + bet[it];
        }
    }
#pragma unroll
    for (int it = 0; it < 4; ++it)
        part[(size_t)slice * (BB * HID) + (b << 10) + tid + it * 256] = acc[it];
}

__global__ __launch_bounds__(256) void final_mean_kernel(
    const float* __restrict__ part, float* __restrict__ out)
{
    const int idx = blockIdx.x * 256 + threadIdx.x;
    float s = 0.f;
#pragma unroll
    for (int p = 0; p < 64; ++p) s += part[(size_t)p * (BB * HID) + idx];
    out[idx] = s * (1.0f / SS);
}

// =============================================================================
// launch
// =============================================================================
extern "C" void kernel_launch(void* const* d_in, const int* in_sizes, int n_in,
                              void* d_out, int out_size)
{
    const float* x1    = (const float*)d_in[0];
    const float* x2    = (const float*)d_in[1];
    const int*   mask  = (const int*)  d_in[2];
    const float* Wq    = (const float*)d_in[3];
    const float* Wk    = (const float*)d_in[4];
    const float* Wv    = (const float*)d_in[5];
    const float* Wo    = (const float*)d_in[6];
    const float* bo    = (const float*)d_in[7];
    const float* gamma = (const float*)d_in[8];
    const float* beta  = (const float*)d_in[9];
    float* out = (float*)d_out;

    void *bx1, *bx2, *bw, *bq, *bkv, *bao, *o2, *part;
    cudaGetSymbolAddress(&bx1, g_bx1);
    cudaGetSymbolAddress(&bx2, g_bx2);
    cudaGetSymbolAddress(&bw,  g_bw);
    cudaGetSymbolAddress(&bq,  g_bq);
    cudaGetSymbolAddress(&bkv, g_bkv);
    cudaGetSymbolAddress(&bao, g_bao);
    cudaGetSymbolAddress(&o2,  g_o2);
    cudaGetSymbolAddress(&part, g_part);

    __nv_bfloat16* bW = (__nv_bfloat16*)bw;

    cudaFuncSetAttribute(gemm_qkv,
        cudaFuncAttributeMaxDynamicSharedMemorySize, GEMM_SMEM);
    cudaFuncSetAttribute(gemm_o,
        cudaFuncAttributeMaxDynamicSharedMemorySize, GEMM_SMEM);
    cudaFuncSetAttribute(attn_bf16,
        cudaFuncAttributeMaxDynamicSharedMemorySize, ATT_SMEM);

    // mask compaction + conversions
    compact_mask<<<BB, 256>>>(mask);
    dim3 gx(MTOT * HID / 1024, 2);
    conv_x<<<gx, 256>>>(x1, x2, (__nv_bfloat16*)bx1, (__nv_bfloat16*)bx2);
    dim3 gw(HID * HID / 1024, 4);
    conv_w<<<gw, 256>>>(Wq, Wk, Wv, Wo, bW);

    const float QSCALE = 0.125f * 1.4426950408889634f;   // 1/sqrt(64) * log2(e)

    // fused Q + KV projections
    dim3 gqkv(8 + 16, MTOT / TBM);           // (24, 32)
    gemm_qkv<<<gqkv, 128, GEMM_SMEM>>>((const __nv_bfloat16*)bx1,
                                       (const __nv_bfloat16*)bx2,
                                       bW, bW + (size_t)HID * HID,
                                       (__nv_bfloat16*)bq, (__nv_bfloat16*)bkv,
                                       QSCALE);

    dim3 ga(SS / 128, NH, BB);               // (8, 16, 4)
    attn_bf16<<<ga, 128, ATT_SMEM>>>((const __nv_bfloat16*)bq,
                                     (const __nv_bfloat16*)bkv,
                                     (__nv_bfloat16*)bao);

    dim3 go(HID / TBN, MTOT / TBM);          // (8, 32)
    gemm_o<<<go, 128, GEMM_SMEM>>>((const __nv_bfloat16*)bao,
                                   bW + (size_t)3 * HID * HID, (float*)o2);

    ln_mean_kernel<<<BB * 64, 256>>>((const float*)o2, x2, bo, gamma, beta, (float*)part);
    final_mean_kernel<<<BB * HID / 256, 256>>>((const float*)part, out);
}

// round 15
// speedup vs baseline: 1.2727x; 1.1396x over previous
#include <cuda_runtime.h>
#include <cuda_bf16.h>
#include <cstdint>

#define BB   4
#define SS   1024
#define HID  1024
#define NH   16
#define HD   64
#define MTOT (BB*SS)

// ---------------- scratch ----------------
__device__ __nv_bfloat16 g_bx1[MTOT*HID];
__device__ __nv_bfloat16 g_bx2[MTOT*HID];
__device__ __nv_bfloat16 g_bw [4*HID*HID];      // Wq,Wk,Wv,Wo (bf16, contiguous)
__device__ __nv_bfloat16 g_bq [MTOT*HID];
__device__ __nv_bfloat16 g_bkv[MTOT*2*HID];     // COMPACTED [K | V] rows, stride 2048
__device__ __nv_bfloat16 g_bao[MTOT*HID];
__device__ float         g_o2 [MTOT*HID];
__device__ float         g_part[64*BB*HID];
__device__ int           g_idx [BB*SS];         // compacted key indices (padded)
__device__ float         g_amask[BB*SS];        // 0 for kept, -1e9 for pad
__device__ int           g_cnt [BB];            // 64-key tile count (even, padded to 128)

// ---------------- helpers ----------------
__device__ __forceinline__ uint32_t f2bf2(float lo, float hi){
    uint32_t r; asm("cvt.rn.bf16x2.f32 %0, %1, %2;" : "=r"(r) : "f"(hi), "f"(lo));
    return r;
}
__device__ __forceinline__ float ex2f(float x){
    float y; asm("ex2.approx.ftz.f32 %0, %1;" : "=f"(y) : "f"(x)); return y;
}
__device__ __forceinline__ void mma_bf16(float* d,
    const uint32_t* a, uint32_t b0, uint32_t b1)
{
    asm volatile(
        "mma.sync.aligned.m16n8k16.row.col.f32.bf16.bf16.f32 "
        "{%0,%1,%2,%3}, {%4,%5,%6,%7}, {%8,%9}, {%0,%1,%2,%3};"
        : "+f"(d[0]), "+f"(d[1]), "+f"(d[2]), "+f"(d[3])
        : "r"(a[0]), "r"(a[1]), "r"(a[2]), "r"(a[3]), "r"(b0), "r"(b1));
}
__device__ __forceinline__ void ldsm_x4(uint32_t* r, uint32_t a){
    asm volatile("ldmatrix.sync.aligned.m8n8.x4.shared.b16 {%0,%1,%2,%3}, [%4];"
                 : "=r"(r[0]), "=r"(r[1]), "=r"(r[2]), "=r"(r[3]) : "r"(a));
}
__device__ __forceinline__ void ldsm_x4t(uint32_t* r, uint32_t a){
    asm volatile("ldmatrix.sync.aligned.m8n8.x4.trans.shared.b16 {%0,%1,%2,%3}, [%4];"
                 : "=r"(r[0]), "=r"(r[1]), "=r"(r[2]), "=r"(r[3]) : "r"(a));
}
__device__ __forceinline__ void cp16(uint32_t dst, const void* src){
    asm volatile("cp.async.cg.shared.global [%0], [%1], 16;" :: "r"(dst), "l"(src));
}
#define CP_COMMIT asm volatile("cp.async.commit_group;" ::: "memory")
#define CP_WAIT1  asm volatile("cp.async.wait_group 1;" ::: "memory")

// =============================================================================
// conversions
// =============================================================================
__global__ __launch_bounds__(256) void conv_x(
    const float* __restrict__ s0, const float* __restrict__ s1,
    __nv_bfloat16* __restrict__ d0, __nv_bfloat16* __restrict__ d1)
{
    const float* s = blockIdx.y ? s1 : s0;
    __nv_bfloat16* d = blockIdx.y ? d1 : d0;
    int i = (blockIdx.x * 256 + threadIdx.x) * 4;
    float4 v = *(const float4*)(s + i);
    *(uint2*)(d + i) = make_uint2(f2bf2(v.x, v.y), f2bf2(v.z, v.w));
}
__global__ __launch_bounds__(256) void conv_w(
    const float* __restrict__ w0, const float* __restrict__ w1,
    const float* __restrict__ w2, const float* __restrict__ w3,
    __nv_bfloat16* __restrict__ d)
{
    const float* s = blockIdx.y == 0 ? w0 : blockIdx.y == 1 ? w1 :
                     blockIdx.y == 2 ? w2 : w3;
    int i = (blockIdx.x * 256 + threadIdx.x) * 4;
    float4 v = *(const float4*)(s + i);
    *(uint2*)(d + (size_t)blockIdx.y * HID * HID + i) =
        make_uint2(f2bf2(v.x, v.y), f2bf2(v.z, v.w));
}

// =============================================================================
// mask compaction: per batch, kept key indices, padded to a 128-multiple.
// Deterministic (stable order). grid = BB blocks x 256 threads.
// =============================================================================
__global__ __launch_bounds__(256) void compact_mask(const int* __restrict__ mask)
{
    const int b = blockIdx.x;
    const int tid = threadIdx.x, lane = tid & 31, wid = tid >> 5;
    __shared__ int wsum[8];

    int m[4], cnt = 0;
    const int base = b * SS + tid * 4;
#pragma unroll
    for (int i = 0; i < 4; ++i) { m[i] = mask[base + i]; cnt += (m[i] != 0); }

    int pre = cnt;
#pragma unroll
    for (int off = 1; off < 32; off <<= 1) {
        int v = __shfl_up_sync(0xffffffffu, pre, off);
        if (lane >= off) pre += v;
    }
    if (lane == 31) wsum[wid] = pre;
    __syncthreads();

    int wbase = 0;
#pragma unroll
    for (int w = 0; w < 8; ++w) if (w < wid) wbase += wsum[w];
    int pos = wbase + pre - cnt;

#pragma unroll
    for (int i = 0; i < 4; ++i) {
        if (m[i]) {
            g_idx[b * SS + pos]   = tid * 4 + i;
            g_amask[b * SS + pos] = 0.f;
            ++pos;
        }
    }

    int total = 0;
#pragma unroll
    for (int w = 0; w < 8; ++w) total += wsum[w];
    const int padded = (total + 127) & ~127;        // 128-multiple for GEMM M-tiles
    for (int j = total + tid; j < padded; j += 256) {
        g_idx[b * SS + j]   = 0;
        g_amask[b * SS + j] = -1e9f;
    }
    if (tid == 0) g_cnt[b] = padded >> 6;           // 64-key tiles (even)
}

// =============================================================================
// bf16 GEMM core: 128x128x64 CTA tile, 4 warps, warp tile 64x64.
// 3 smem buffers, prefetch distance 2, ONE syncthreads per chunk.
// GATHER: A rows indirected through aidx (for compacted-KV projection).
// =============================================================================
#define TBM 128
#define TBN 128
#define TBK 64
#define GPD 72
#define NBUF 3
#define NCH (HID/TBK)                        // 16
#define GEMM_SMEM (NBUF*(TBM+TBN)*GPD*2)     // 110592

template<bool GATHER>
__device__ __forceinline__ void gemm_stage(
    const __nv_bfloat16* __restrict__ A, const __nv_bfloat16* __restrict__ W,
    const int* __restrict__ aidx,
    int bm, int bn, int kt, int buf, int tid, uint32_t uBase)
{
    const int k0 = kt * TBK;
    const uint32_t uA = uBase + (uint32_t)buf * TBM * GPD * 2;
    const uint32_t uB = uBase + (uint32_t)(NBUF * TBM + buf * TBN) * GPD * 2;
#pragma unroll
    for (int i = 0; i < 8; ++i) {
        int idx = tid + i * 128;
        int row = idx >> 3, cc = (idx & 7) * 8;
        const __nv_bfloat16* arow = GATHER
            ? A + (size_t)aidx[bm + row] * HID
            : A + (size_t)(bm + row) * HID;
        cp16(uA + (uint32_t)(row * GPD + cc) * 2, arow + k0 + cc);
        cp16(uB + (uint32_t)(row * GPD + cc) * 2,
             W + (size_t)(bn + row) * HID + k0 + cc);
    }
}

__device__ __forceinline__ void gemm_load_frags(
    uint32_t af[4][4], uint32_t bf[4][4],
    uint32_t uA, uint32_t uB, int kk, int wm, int wn, int lane)
{
#pragma unroll
    for (int mt = 0; mt < 4; ++mt) {
        int row = wm + mt * 16 + (lane & 15);
        int col = kk + ((lane >> 4) << 3);
        ldsm_x4(af[mt], uA + (uint32_t)(row * GPD + col) * 2);
    }
#pragma unroll
    for (int np = 0; np < 4; ++np) {
        int row = wn + np * 16 + ((lane & 16) >> 1) + (lane & 7);
        int col = kk + (lane & 8);
        ldsm_x4(bf[np], uB + (uint32_t)(row * GPD + col) * 2);
    }
}

template<bool OBF, bool GATHER>
__device__ __forceinline__ void gemm_core(
    const __nv_bfloat16* __restrict__ A, const __nv_bfloat16* __restrict__ W,
    const int* __restrict__ aidx,
    void* __restrict__ Cv, int ldc, float scale, int bm, int bn, uint32_t uBase)
{
    const int tid = threadIdx.x, lane = tid & 31, wid = tid >> 5;
    const int wm = (wid & 1) * 64, wn = (wid >> 1) * 64;
    const int g = lane >> 2, t4 = lane & 3;

    float acc[4][8][4];
#pragma unroll
    for (int mt = 0; mt < 4; ++mt)
#pragma unroll
        for (int nt = 0; nt < 8; ++nt)
#pragma unroll
            for (int i = 0; i < 4; ++i) acc[mt][nt][i] = 0.f;

#pragma unroll
    for (int p = 0; p < 2; ++p) {
        gemm_stage<GATHER>(A, W, aidx, bm, bn, p, p, tid, uBase);
        CP_COMMIT;
    }

    uint32_t af[2][4][4], bf[2][4][4];

    for (int kt = 0; kt < NCH; ++kt) {
        const int buf = kt % NBUF;
        const uint32_t uA = uBase + (uint32_t)buf * TBM * GPD * 2;
        const uint32_t uB = uBase + (uint32_t)(NBUF * TBM + buf * TBN) * GPD * 2;

        CP_WAIT1;
        __syncthreads();

        if (kt + 2 < NCH)
            gemm_stage<GATHER>(A, W, aidx, bm, bn, kt + 2, (kt + 2) % NBUF, tid, uBase);
        CP_COMMIT;

        gemm_load_frags(af[0], bf[0], uA, uB, 0, wm, wn, lane);

#pragma unroll
        for (int ks = 0; ks < 4; ++ks) {
            const int cur = ks & 1;
            if (ks < 3)
                gemm_load_frags(af[cur ^ 1], bf[cur ^ 1], uA, uB,
                                (ks + 1) * 16, wm, wn, lane);
#pragma unroll
            for (int mt = 0; mt < 4; ++mt)
#pragma unroll
                for (int np = 0; np < 4; ++np) {
                    mma_bf16(acc[mt][2 * np],     af[cur][mt], bf[cur][np][0], bf[cur][np][1]);
                    mma_bf16(acc[mt][2 * np + 1], af[cur][mt], bf[cur][np][2], bf[cur][np][3]);
                }
        }
    }

    if (OBF) {
        __nv_bfloat16* C = (__nv_bfloat16*)Cv;
#pragma unroll
        for (int mt = 0; mt < 4; ++mt) {
            int r0 = bm + wm + mt * 16 + g;
#pragma unroll
            for (int nt = 0; nt < 8; ++nt) {
                int c = bn + wn + nt * 8 + 2 * t4;
                *(uint32_t*)(C + (size_t)r0 * ldc + c) =
                    f2bf2(acc[mt][nt][0] * scale, acc[mt][nt][1] * scale);
                *(uint32_t*)(C + (size_t)(r0 + 8) * ldc + c) =
                    f2bf2(acc[mt][nt][2] * scale, acc[mt][nt][3] * scale);
            }
        }
    } else {
        float* C = (float*)Cv;
#pragma unroll
        for (int mt = 0; mt < 4; ++mt) {
            int r0 = bm + wm + mt * 16 + g;
#pragma unroll
            for (int nt = 0; nt < 8; ++nt) {
                int c = bn + wn + nt * 8 + 2 * t4;
                *(float2*)(C + (size_t)r0 * ldc + c)       = make_float2(acc[mt][nt][0], acc[mt][nt][1]);
                *(float2*)(C + (size_t)(r0 + 8) * ldc + c) = make_float2(acc[mt][nt][2], acc[mt][nt][3]);
            }
        }
    }
}

// fused Q + compacted-KV projection.
// blockIdx.x < 8: Q tiles (full M=4096). blockIdx.x in [8,24): KV N-tile,
// blockIdx.y -> (b, local M-tile); CTAs past the padded row count exit.
__global__ __launch_bounds__(128, 2) void gemm_qkv(
    const __nv_bfloat16* __restrict__ x1, const __nv_bfloat16* __restrict__ x2,
    const __nv_bfloat16* __restrict__ Wq, const __nv_bfloat16* __restrict__ Wkv,
    __nv_bfloat16* __restrict__ Cq, __nv_bfloat16* __restrict__ Ckv, float qscale)
{
    extern __shared__ __nv_bfloat16 smg[];
    const uint32_t uBase = (uint32_t)__cvta_generic_to_shared(smg);
    if (blockIdx.x < 8) {
        gemm_core<true, false>(x1, Wq, nullptr, Cq, HID, qscale,
                               blockIdx.y * TBM, blockIdx.x * TBN, uBase);
    } else {
        const int b = blockIdx.y >> 3, mtile = blockIdx.y & 7;
        const int rows = g_cnt[b] << 6;          // padded (multiple of 128)
        if (mtile * TBM >= rows) return;
        gemm_core<true, true>(x2 + (size_t)(b * SS) * HID, Wkv,
                              g_idx + b * SS,
                              Ckv + (size_t)(b * SS) * 2048, 2 * HID, 1.0f,
                              mtile * TBM, (blockIdx.x - 8) * TBN, uBase);
    }
}

// O projection (fp32 out)
__global__ __launch_bounds__(128, 2) void gemm_o(
    const __nv_bfloat16* __restrict__ A, const __nv_bfloat16* __restrict__ W,
    float* __restrict__ C)
{
    extern __shared__ __nv_bfloat16 smg[];
    const uint32_t uBase = (uint32_t)__cvta_generic_to_shared(smg);
    gemm_core<false, false>(A, W, nullptr, C, HID, 1.0f,
                            blockIdx.y * TBM, blockIdx.x * TBN, uBase);
}

// =============================================================================
// bf16 flash attention over COMPACTED contiguous K/V rows.
// 4 warps x 32 query rows, 64-key tiles, 3 smem buffers, 1 sync per tile.
// grid (S1/128, H, B)
// =============================================================================
#define ANBUF 3
#define KP 72
#define AKV (64*KP*2)
#define ATT_SMEM (ANBUF*2*AKV + ANBUF*64*4) // 56064

__device__ __forceinline__ void attn_stage(
    const __nv_bfloat16* __restrict__ Kb, const __nv_bfloat16* __restrict__ Vb,
    const float* __restrict__ abase, int t0, int buf, int tid,
    uint32_t uK, uint32_t uV, float* mskf)
{
#pragma unroll
    for (int i = 0; i < 4; ++i) {
        int idx = tid + i * 128;
        int row = idx >> 3, cc = (idx & 7) * 8;
        cp16(uK + (uint32_t)((buf * 64 + row) * KP + cc) * 2,
             Kb + (size_t)(t0 + row) * 2048 + cc);
        cp16(uV + (uint32_t)((buf * 64 + row) * KP + cc) * 2,
             Vb + (size_t)(t0 + row) * 2048 + cc);
    }
    if (tid < 64) mskf[buf * 64 + tid] = abase[t0 + tid];
}

__global__ __launch_bounds__(128, 2) void attn_bf16(
    const __nv_bfloat16* __restrict__ Q, const __nv_bfloat16* __restrict__ KVg,
    __nv_bfloat16* __restrict__ O)
{
    extern __shared__ char sma[];
    const uint32_t uK = (uint32_t)__cvta_generic_to_shared(sma);
    const uint32_t uV = uK + ANBUF * AKV;
    float* mskf = (float*)(sma + 2 * ANBUF * AKV);

    const int m0 = blockIdx.x * 128;
    const int h  = blockIdx.y, b = blockIdx.z;
    const int tid = threadIdx.x, lane = tid & 31, wid = tid >> 5;
    const int g = lane >> 2, t4 = lane & 3;

    const int ntiles = g_cnt[b];
    const float* abase = g_amask + b * SS;

    uint32_t qa[4][2][4];
    const __nv_bfloat16* Qb = Q + (size_t)(b * SS + m0 + wid * 32) * HID + h * HD;
#pragma unroll
    for (int kc = 0; kc < 4; ++kc) {
        int k0 = kc * 16 + t4 * 2;
#pragma unroll
        for (int mt = 0; mt < 2; ++mt) {
            const __nv_bfloat16* Qm = Qb + (size_t)(mt * 16) * HID;
            qa[kc][mt][0] = *(const uint32_t*)(Qm + (size_t)g * HID + k0);
            qa[kc][mt][1] = *(const uint32_t*)(Qm + (size_t)(g + 8) * HID + k0);
            qa[kc][mt][2] = *(const uint32_t*)(Qm + (size_t)g * HID + k0 + 8);
            qa[kc][mt][3] = *(const uint32_t*)(Qm + (size_t)(g + 8) * HID + k0 + 8);
        }
    }

    float oacc[2][8][4];
#pragma unroll
    for (int mt = 0; mt < 2; ++mt)
#pragma unroll
        for (int nt = 0; nt < 8; ++nt)
#pragma unroll
            for (int i = 0; i < 4; ++i) oacc[mt][nt][i] = 0.f;
    float lp[2][2] = {{0.f, 0.f}, {0.f, 0.f}};

    const __nv_bfloat16* Kb = KVg + (size_t)(b * SS) * 2048 + h * HD;
    const __nv_bfloat16* Vb = Kb + 1024;

    for (int p = 0; p < 2 && p < ntiles; ++p) {
        attn_stage(Kb, Vb, abase, p * 64, p, tid, uK, uV, mskf);
        CP_COMMIT;
    }

    for (int t = 0; t < ntiles; ++t) {
        const int buf = t % ANBUF;
        CP_WAIT1;
        __syncthreads();

        if (t + 2 < ntiles)
            attn_stage(Kb, Vb, abase, (t + 2) * 64, (t + 2) % ANBUF,
                       tid, uK, uV, mskf);
        CP_COMMIT;

        // ---- S = Q K^T : per warp 32x64 ----
        float sacc[2][8][4];
#pragma unroll
        for (int mt = 0; mt < 2; ++mt)
#pragma unroll
            for (int nt = 0; nt < 8; ++nt)
#pragma unroll
                for (int i = 0; i < 4; ++i) sacc[mt][nt][i] = 0.f;
#pragma unroll
        for (int ks = 0; ks < 4; ++ks) {
            const int kk = ks * 16;
#pragma unroll
            for (int np = 0; np < 4; ++np) {
                int row = buf * 64 + np * 16 + ((lane & 16) >> 1) + (lane & 7);
                int col = kk + (lane & 8);
                uint32_t bfr[4];
                ldsm_x4(bfr, uK + (uint32_t)(row * KP + col) * 2);
#pragma unroll
                for (int mt = 0; mt < 2; ++mt) {
                    mma_bf16(sacc[mt][2 * np],     qa[ks][mt], bfr[0], bfr[1]);
                    mma_bf16(sacc[mt][2 * np + 1], qa[ks][mt], bfr[2], bfr[3]);
                }
            }
        }

        // ---- p = exp2(s + amask) ----
#pragma unroll
        for (int mt = 0; mt < 2; ++mt)
#pragma unroll
            for (int nt = 0; nt < 8; ++nt) {
                int c = nt * 8 + 2 * t4;
                float a0 = mskf[buf * 64 + c], a1 = mskf[buf * 64 + c + 1];
                sacc[mt][nt][0] = ex2f(sacc[mt][nt][0] + a0);
                sacc[mt][nt][1] = ex2f(sacc[mt][nt][1] + a1);
                sacc[mt][nt][2] = ex2f(sacc[mt][nt][2] + a0);
                sacc[mt][nt][3] = ex2f(sacc[mt][nt][3] + a1);
                lp[mt][0] += sacc[mt][nt][0] + sacc[mt][nt][1];
                lp[mt][1] += sacc[mt][nt][2] + sacc[mt][nt][3];
            }

        // ---- O += P V (P in registers) ----
#pragma unroll
        for (int kt = 0; kt < 4; ++kt) {
            uint32_t pf[2][4];
#pragma unroll
            for (int mt = 0; mt < 2; ++mt) {
                pf[mt][0] = f2bf2(sacc[mt][2 * kt][0],     sacc[mt][2 * kt][1]);
                pf[mt][1] = f2bf2(sacc[mt][2 * kt][2],     sacc[mt][2 * kt][3]);
                pf[mt][2] = f2bf2(sacc[mt][2 * kt + 1][0], sacc[mt][2 * kt + 1][1]);
                pf[mt][3] = f2bf2(sacc[mt][2 * kt + 1][2], sacc[mt][2 * kt + 1][3]);
            }
#pragma unroll
            for (int dtp = 0; dtp < 4; ++dtp) {
                int row = buf * 64 + kt * 16 + (lane & 15);
                int col = dtp * 16 + ((lane >> 4) & 1) * 8;
                uint32_t bfr[4];
                ldsm_x4t(bfr, uV + (uint32_t)(row * KP + col) * 2);
#pragma unroll
                for (int mt = 0; mt < 2; ++mt) {
                    mma_bf16(oacc[mt][2 * dtp],     pf[mt], bfr[0], bfr[1]);
                    mma_bf16(oacc[mt][2 * dtp + 1], pf[mt], bfr[2], bfr[3]);
                }
            }
        }
    }

    // l reduction over 4-lane groups
#pragma unroll
    for (int mt = 0; mt < 2; ++mt)
#pragma unroll
        for (int rr = 0; rr < 2; ++rr) {
            lp[mt][rr] += __shfl_xor_sync(0xffffffffu, lp[mt][rr], 1);
            lp[mt][rr] += __shfl_xor_sync(0xffffffffu, lp[mt][rr], 2);
        }

    __nv_bfloat16* Ob = O + (size_t)(b * SS + m0 + wid * 32) * HID + h * HD;
#pragma unroll
    for (int mt = 0; mt < 2; ++mt) {
        const float inv0 = 1.0f / lp[mt][0], inv1 = 1.0f / lp[mt][1];
#pragma unroll
        for (int dt = 0; dt < 8; ++dt) {
            int c = dt * 8 + 2 * t4;
            *(uint32_t*)(Ob + (size_t)(mt * 16 + g) * HID + c) =
                f2bf2(oacc[mt][dt][0] * inv0, oacc[mt][dt][1] * inv0);
            *(uint32_t*)(Ob + (size_t)(mt * 16 + g + 8) * HID + c) =
                f2bf2(oacc[mt][dt][2] * inv1, oacc[mt][dt][3] * inv1);
        }
    }
}

// =============================================================================
// Fused (+bo +x_cls) LayerNorm + partial mean — two-phase, 1 block sync.
// =============================================================================
__global__ __launch_bounds__(256) void ln_mean_kernel(
    const float* __restrict__ O2, const float* __restrict__ x2,
    const float* __restrict__ bo, const float* __restrict__ gamma,
    const float* __restrict__ beta, float* __restrict__ part)
{
    const int blk = blockIdx.x;
    const int b = blk >> 6, slice = blk & 63;
    const int tid = threadIdx.x, lane = tid & 31, wid = tid >> 5;

    __shared__ float smu[16], sinv[16];
    const float* xc = x2 + (size_t)b * SS * HID;
    const int row0 = (b << 10) + (slice << 4);

#pragma unroll
    for (int rr = 0; rr < 2; ++rr) {
        const int t = wid + rr * 8;
        const float* o = O2 + (size_t)(row0 + t) * HID;
        float s = 0.f, ss = 0.f;
#pragma unroll
        for (int k = 0; k < 32; ++k) {
            int j = lane + k * 32;
            float y = o[j] + bo[j] + xc[j];
            s += y; ss += y * y;
        }
#pragma unroll
        for (int off = 16; off; off >>= 1) {
            s  += __shfl_xor_sync(0xffffffffu, s,  off);
            ss += __shfl_xor_sync(0xffffffffu, ss, off);
        }
        if (lane == 0) {
            float mu  = s * (1.0f / HID);
            float var = ss * (1.0f / HID) - mu * mu;
            smu[t]  = mu;
            sinv[t] = rsqrtf(var + 1e-5f);
        }
    }
    __syncthreads();

    float add[4], gam[4], bet[4], acc[4] = {0.f, 0.f, 0.f, 0.f};
#pragma unroll
    for (int it = 0; it < 4; ++it) {
        int j = tid + it * 256;
        add[it] = bo[j] + xc[j];
        gam[it] = gamma[j];
        bet[it] = beta[j];
    }
    for (int t = 0; t < 16; ++t) {
        const float* o = O2 + (size_t)(row0 + t) * HID;
        const float mu = smu[t], inv = sinv[t];
#pragma unroll
        for (int it = 0; it < 4; ++it) {
            float y = o[tid + it * 256] + add[it];
            acc[it] += (y - mu) * inv * gam[it] + bet[it];
        }
    }
#pragma unroll
    for (int it = 0; it < 4; ++it)
        part[(size_t)slice * (BB * HID) + (b << 10) + tid + it * 256] = acc[it];
}

__global__ __launch_bounds__(256) void final_mean_kernel(
    const float* __restrict__ part, float* __restrict__ out)
{
    const int idx = blockIdx.x * 256 + threadIdx.x;
    float s = 0.f;
#pragma unroll
    for (int p = 0; p < 64; ++p) s += part[(size_t)p * (BB * HID) + idx];
    out[idx] = s * (1.0f / SS);
}

// =============================================================================
// launch
// =============================================================================
extern "C" void kernel_launch(void* const* d_in, const int* in_sizes, int n_in,
                              void* d_out, int out_size)
{
    const float* x1    = (const float*)d_in[0];
    const float* x2    = (const float*)d_in[1];
    const int*   mask  = (const int*)  d_in[2];
    const float* Wq    = (const float*)d_in[3];
    const float* Wk    = (const float*)d_in[4];
    const float* Wv    = (const float*)d_in[5];
    const float* Wo    = (const float*)d_in[6];
    const float* bo    = (const float*)d_in[7];
    const float* gamma = (const float*)d_in[8];
    const float* beta  = (const float*)d_in[9];
    float* out = (float*)d_out;

    void *bx1, *bx2, *bw, *bq, *bkv, *bao, *o2, *part;
    cudaGetSymbolAddress(&bx1, g_bx1);
    cudaGetSymbolAddress(&bx2, g_bx2);
    cudaGetSymbolAddress(&bw,  g_bw);
    cudaGetSymbolAddress(&bq,  g_bq);
    cudaGetSymbolAddress(&bkv, g_bkv);
    cudaGetSymbolAddress(&bao, g_bao);
    cudaGetSymbolAddress(&o2,  g_o2);
    cudaGetSymbolAddress(&part, g_part);

    __nv_bfloat16* bW = (__nv_bfloat16*)bw;

    cudaFuncSetAttribute(gemm_qkv,
        cudaFuncAttributeMaxDynamicSharedMemorySize, GEMM_SMEM);
    cudaFuncSetAttribute(gemm_o,
        cudaFuncAttributeMaxDynamicSharedMemorySize, GEMM_SMEM);
    cudaFuncSetAttribute(attn_bf16,
        cudaFuncAttributeMaxDynamicSharedMemorySize, ATT_SMEM);

    // mask compaction + conversions
    compact_mask<<<BB, 256>>>(mask);
    dim3 gx(MTOT * HID / 1024, 2);
    conv_x<<<gx, 256>>>(x1, x2, (__nv_bfloat16*)bx1, (__nv_bfloat16*)bx2);
    dim3 gw(HID * HID / 1024, 4);
    conv_w<<<gw, 256>>>(Wq, Wk, Wv, Wo, bW);

    const float QSCALE = 0.125f * 1.4426950408889634f;   // 1/sqrt(64) * log2(e)

    // fused Q + compacted-KV projections
    dim3 gqkv(8 + 16, MTOT / TBM);           // (24, 32)
    gemm_qkv<<<gqkv, 128, GEMM_SMEM>>>((const __nv_bfloat16*)bx1,
                                       (const __nv_bfloat16*)bx2,
                                       bW, bW + (size_t)HID * HID,
                                       (__nv_bfloat16*)bq, (__nv_bfloat16*)bkv,
                                       QSCALE);

    dim3 ga(SS / 128, NH, BB);               // (8, 16, 4)
    attn_bf16<<<ga, 128, ATT_SMEM>>>((const __nv_bfloat16*)bq,
                                     (const __nv_bfloat16*)bkv,
                                     (__nv_bfloat16*)bao);

    dim3 go(HID / TBN, MTOT / TBM);          // (8, 32)
    gemm_o<<<go, 128, GEMM_SMEM>>>((const __nv_bfloat16*)bao,
                                   bW + (size_t)3 * HID * HID, (float*)o2);

    ln_mean_kernel<<<BB * 64, 256>>>((const float*)o2, x2, bo, gamma, beta, (float*)part);
    final_mean_kernel<<<BB * HID / 256, 256>>>((const float*)part, out);
}